// round 10
// baseline (speedup 1.0000x reference)
#include <cuda_runtime.h>
#include <cuda_fp16.h>
#include <stdint.h>

#define NNODES 4096
#define NEDGES 32768
#define NSC 48
#define NVC 16
#define NEF 128
#define WNUM 4096
#define BN_EPS 1e-5f
#define INV_SQRT3 0.57735026918962576f
#define ALPHA 0.125f

#define NCHUNKS 64
#define KSTEPS 9                              // 8 data ksteps (K=16) + 1 bias kstep
#define BFRAG_PER_CHUNK (KSTEPS * 8 * 32)     // uint2 entries = 2304
#define NBF_TOTAL (NCHUNKS * BFRAG_PER_CHUNK) // 147456
#define NW1F 4608                             // 9 ksteps * 16 n8 * 32 lanes

// ---------------- static device scratch ----------------
__device__ __align__(16) uint2 g_Bfrag[NBF_TOTAL]; // fp16 W2 fragment images
__device__ __align__(16) uint2 g_W1frag[NW1F];     // fp16 W1+b1 fragment images
__device__ float g_accum[NNODES * 96];
__device__ float g_mean[NSC];
__device__ float g_rs[NSC];
__device__ float g_rsv[NVC];
__device__ int g_src[NEDGES];
__device__ int g_dst[NEDGES];
__device__ int g_mode;

// ================= helpers =================
__device__ __forceinline__ uint32_t smem_u32(const void* p) {
    uint32_t a;
    asm("{ .reg .u64 t; cvta.to.shared.u64 t, %1; cvt.u32.u64 %0, t; }" : "=r"(a) : "l"(p));
    return a;
}
__device__ __forceinline__ void mma16(float* d, const uint32_t* a, uint32_t b0, uint32_t b1) {
    asm volatile(
        "mma.sync.aligned.m16n8k16.row.col.f32.f16.f16.f32 "
        "{%0,%1,%2,%3}, {%4,%5,%6,%7}, {%8,%9}, {%0,%1,%2,%3};\n"
        : "+f"(d[0]), "+f"(d[1]), "+f"(d[2]), "+f"(d[3])
        : "r"(a[0]), "r"(a[1]), "r"(a[2]), "r"(a[3]), "r"(b0), "r"(b1));
}
__device__ __forceinline__ void cpa16(uint32_t s, const void* g) {
    asm volatile("cp.async.ca.shared.global [%0], [%1], 16;" :: "r"(s), "l"(g));
}
#define CP_COMMIT() asm volatile("cp.async.commit_group;" ::: "memory")
#define CP_WAIT0()  asm volatile("cp.async.wait_group 0;" ::: "memory")

__device__ __forceinline__ float dlrelu(float x) { return (fabsf(x) <= 10.f) ? x : 0.01f * x; }
__device__ __forceinline__ uint32_t pack_relu(float a, float b) {
    __half2 h = __floats2half2_rn(fmaxf(a, 0.f), fmaxf(b, 0.f));
    return *reinterpret_cast<uint32_t*>(&h);
}

// column permutation: jp (permuted) -> original j of fc_w2
__device__ __forceinline__ int jorig_of(int jp) {
    int chunk = jp >> 6, q = jp & 63;
    if (chunk < 48) {
        return (q < 48) ? q * 48 + chunk : 2304 + (q - 48) * 48 + chunk;
    }
    int k = chunk - 48;
    return (q < 48) ? 3072 + q * 16 + k : 3840 + (q - 48) * 16 + k;
}

// ================= small prep kernels =================
__global__ void k_detect_idx(const int* __restrict__ raw) {
    __shared__ int flag;
    int t = threadIdx.x;
    if (t == 0) flag = 0;
    __syncthreads();
    for (int i = t; i < 2048; i += 256)
        if (raw[2 * i + 1] != 0) flag = 1;
    __syncthreads();
    if (t == 0) g_mode = flag;
}
// idx convert + accumulator init (merged)
__global__ void k_misc(const int* __restrict__ raw, const float* __restrict__ na) {
    int idx = blockIdx.x * 256 + threadIdx.x;
    if (idx < NEDGES) {
        if (g_mode) { g_src[idx] = raw[idx]; g_dst[idx] = raw[NEDGES + idx]; }
        else        { g_src[idx] = raw[2 * idx]; g_dst[idx] = raw[2 * (NEDGES + idx)]; }
    }
    if (idx < NNODES * 96) g_accum[idx] = na[idx];
}
// build fp16 fragment images for W2 (permuted, read directly from w2) and W1(+biases)
__global__ void k_prep_frags(const float* __restrict__ w2,
                             const float* __restrict__ b2,
                             const float* __restrict__ w1,
                             const float* __restrict__ b1) {
    int idx = blockIdx.x * 256 + threadIdx.x;
    if (idx < NBF_TOTAL) {
        int lane = idx & 31;
        int g8 = (idx >> 5) & 7;
        int rest = idx >> 8;        // chunk*9 + s
        int s = rest % KSTEPS, chunk = rest / KSTEPS;
        int q = g8 * 8 + (lane >> 2);
        int jo = jorig_of(chunk * 64 + q);
        int k0 = s * 16 + (lane & 3) * 2;
        float f[4];
#pragma unroll
        for (int r = 0; r < 4; ++r) {
            int k = k0 + (r >> 1) * 8 + (r & 1);
            f[r] = (k < 128) ? w2[(size_t)k * WNUM + jo] : ((k == 128) ? b2[jo] : 0.f);
        }
        uint2 out;
        __half2 h0 = __floats2half2_rn(f[0], f[1]);
        __half2 h1 = __floats2half2_rn(f[2], f[3]);
        out.x = *reinterpret_cast<uint32_t*>(&h0);
        out.y = *reinterpret_cast<uint32_t*>(&h1);
        g_Bfrag[idx] = out;
    } else if (idx < NBF_TOTAL + NW1F) {
        int v = idx - NBF_TOTAL;
        int lane = v & 31;
        int g = (v >> 5) & 15;
        int s = v >> 9;             // 0..8
        int col = g * 8 + (lane >> 2);
        int k0 = s * 16 + (lane & 3) * 2;
        float f[4];
#pragma unroll
        for (int r = 0; r < 4; ++r) {
            int k = k0 + (r >> 1) * 8 + (r & 1);
            f[r] = (k < 128) ? w1[k * 128 + col] : ((k == 128) ? b1[col] : 0.f);
        }
        uint2 out;
        __half2 h0 = __floats2half2_rn(f[0], f[1]);
        __half2 h1 = __floats2half2_rn(f[2], f[3]);
        out.x = *reinterpret_cast<uint32_t*>(&h0);
        out.y = *reinterpret_cast<uint32_t*>(&h1);
        g_W1frag[v] = out;
    }
}

// ================= fused stage-A + fp16 mma GEMM + tensor product + scatter =================
struct SmemT {
    uint2 B[2][BFRAG_PER_CHUNK];   // 36864 B — holds W1frag during prologue
    float xs[64][49];              // xs/xv area doubles as ea_h (18432 B) during prologue
    float xv[64][49];
    float dotv[64][17];
    float sss[64];
    float sv[64][3];
    int dst[64];
};

extern __shared__ __align__(16) char smemraw[];

__global__ __launch_bounds__(128, 3) void k_tp(const float* __restrict__ na,
                                               const float* __restrict__ sh,
                                               const float* __restrict__ ea) {
    SmemT& sm = *reinterpret_cast<SmemT*>(smemraw);
    int t = threadIdx.x, lane = t & 31, w = t >> 5;
    int h = w & 1;                 // n-half
    int mb = (w >> 1) * 32;        // m-block base (32 edges)
    int ebase = blockIdx.x * 64;
    int r = lane >> 2, q = lane & 3;
    uint32_t one = (q == 0) ? 0x00003c00u : 0u;   // half2(1, 0)

    // ---- 1: stream W1 fragment images into the B double-buffer area ----
    {
        uint32_t sB = smem_u32(&sm.B[0][0]);
        const char* g = (const char*)g_W1frag;
#pragma unroll
        for (int i = 0; i < 18; ++i) cpa16(sB + (t + 128 * i) * 16, g + (t + 128 * i) * 16);
        CP_COMMIT();
    }
    // ---- 2: ea tile -> fp16 permuted smem image (overlaying xs/xv) ----
    __half* eah = reinterpret_cast<__half*>(&sm.xs[0][0]);
    for (int i = t; i < 64 * 64; i += 128) {
        int e = i >> 6, c = (i & 63) * 2;
        float2 v = *reinterpret_cast<const float2*>(ea + (size_t)(ebase + e) * 128 + c);
        int s = c >> 4, ww = c & 15;
        int pos = ((ww & 7) >> 1) * 4 + ((ww >> 3) << 1);
        __half2 hp = __floats2half2_rn(v.x, v.y);
        *reinterpret_cast<__half2*>(eah + e * 144 + s * 16 + pos) = hp;
    }
    CP_WAIT0();
    __syncthreads();

    // ---- 3: prologue MMA — compute H fragments (A frags for main loop) ----
    uint32_t afr[2][8][4];
    const uint2* w1f = reinterpret_cast<const uint2*>(&sm.B[0][0]);
#pragma unroll
    for (int mt = 0; mt < 2; ++mt) {
        float accH[16][4];
#pragma unroll
        for (int g = 0; g < 16; ++g)
            accH[g][0] = accH[g][1] = accH[g][2] = accH[g][3] = 0.f;
        const __half* row0 = eah + (mb + mt * 16 + r) * 144;
        const __half* row8 = row0 + 8 * 144;
#pragma unroll 1
        for (int s = 0; s < KSTEPS; ++s) {
            uint32_t af[4];
            if (s < 8) {
                uint2 ae0 = *reinterpret_cast<const uint2*>(row0 + s * 16 + q * 4);
                uint2 ae1 = *reinterpret_cast<const uint2*>(row8 + s * 16 + q * 4);
                af[0] = ae0.x; af[1] = ae1.x; af[2] = ae0.y; af[3] = ae1.y;
            } else {
                af[0] = one; af[1] = one; af[2] = 0u; af[3] = 0u;
            }
#pragma unroll
            for (int g = 0; g < 16; ++g) {
                uint2 bf = w1f[(s * 16 + g) * 32 + lane];
                mma16(accH[g], af, bf.x, bf.y);
            }
        }
#pragma unroll
        for (int sp = 0; sp < 8; ++sp) {
            afr[mt][sp][0] = pack_relu(accH[2 * sp][0], accH[2 * sp][1]);
            afr[mt][sp][1] = pack_relu(accH[2 * sp][2], accH[2 * sp][3]);
            afr[mt][sp][2] = pack_relu(accH[2 * sp + 1][0], accH[2 * sp + 1][1]);
            afr[mt][sp][3] = pack_relu(accH[2 * sp + 1][2], accH[2 * sp + 1][3]);
        }
    }
    __syncthreads();   // all warps done reading W1frag / ea_h

    // ---- 4: per-edge node data (overwrites dead ea_h region after prologue) ----
    if (t < 64) {
        int e = ebase + t;
        sm.dst[t] = g_dst[e];
        float4 shv = __ldg(reinterpret_cast<const float4*>(sh) + e);
        sm.sss[t] = shv.x;
        sm.sv[t][0] = shv.y; sm.sv[t][1] = shv.z; sm.sv[t][2] = shv.w;
        const float4* nr = reinterpret_cast<const float4*>(na + (size_t)g_src[e] * 96);
#pragma unroll
        for (int qq = 0; qq < 24; ++qq) {
            float4 v = __ldg(nr + qq);
            float vv[4] = {v.x, v.y, v.z, v.w};
#pragma unroll
            for (int j = 0; j < 4; ++j) {
                int c = qq * 4 + j;
                if (c < 48) sm.xs[t][c] = vv[j];
                else sm.xv[t][c - 48] = vv[j];
            }
        }
#pragma unroll
        for (int i = 0; i < 16; ++i)
            sm.dotv[t][i] = INV_SQRT3 * (sm.xv[t][3 * i + 0] * shv.y +
                                         sm.xv[t][3 * i + 1] * shv.z +
                                         sm.xv[t][3 * i + 2] * shv.w);
    }

    // ---- 5: pipelined main loop (epilogue shifted one chunk back) ----
    float accE[2][4][4], accO[2][4][4];

    auto prefetch = [&](int c, int buf) {
        if (c < NCHUNKS) {
            uint32_t sB = smem_u32(&sm.B[buf][0]);
            const char* g = (const char*)(g_Bfrag + (size_t)c * BFRAG_PER_CHUNK);
#pragma unroll
            for (int i = 0; i < 9; ++i) cpa16(sB + (t + 128 * i) * 16, g + (t + 128 * i) * 16);
        }
        CP_COMMIT();
    };
    auto do_mma = [&](int buf, float (&acc)[2][4][4]) {
#pragma unroll
        for (int mt = 0; mt < 2; ++mt)
#pragma unroll
            for (int b = 0; b < 4; ++b)
#pragma unroll
                for (int rr = 0; rr < 4; ++rr) acc[mt][b][rr] = 0.f;
#pragma unroll
        for (int s = 0; s < 8; ++s) {
#pragma unroll
            for (int b = 0; b < 4; ++b) {
                uint2 bf = sm.B[buf][(s * 8 + h * 4 + b) * 32 + lane];
                mma16(acc[0][b], afr[0][s], bf.x, bf.y);
                mma16(acc[1][b], afr[1][s], bf.x, bf.y);
            }
        }
        uint32_t af1[4] = {one, one, 0u, 0u};
#pragma unroll
        for (int b = 0; b < 4; ++b) {
            uint2 bf = sm.B[buf][(8 * 8 + h * 4 + b) * 32 + lane];
            mma16(acc[0][b], af1, bf.x, bf.y);
            mma16(acc[1][b], af1, bf.x, bf.y);
        }
    };
    auto epilogue = [&](int c, float (&acc)[2][4][4]) {
        if (c < 48) {
            float pxs[2][2] = {{0.f, 0.f}, {0.f, 0.f}};
            float pdot[2][2] = {{0.f, 0.f}, {0.f, 0.f}};
#pragma unroll
            for (int mt = 0; mt < 2; ++mt) {
                int el0 = mb + mt * 16 + r;
#pragma unroll
                for (int b = 0; b < 4; ++b) {
                    int g8 = h * 4 + b;
                    int q0 = g8 * 8 + q * 2;
                    float w00 = dlrelu(acc[mt][b][0]), w01 = dlrelu(acc[mt][b][1]);
                    float w10 = dlrelu(acc[mt][b][2]), w11 = dlrelu(acc[mt][b][3]);
                    if (g8 < 6) {
                        pxs[mt][0] += sm.xs[el0][q0] * w00 + sm.xs[el0][q0 + 1] * w01;
                        pxs[mt][1] += sm.xs[el0 + 8][q0] * w10 + sm.xs[el0 + 8][q0 + 1] * w11;
                    } else {
                        int i0 = q0 - 48;
                        pdot[mt][0] += sm.dotv[el0][i0] * w00 + sm.dotv[el0][i0 + 1] * w01;
                        pdot[mt][1] += sm.dotv[el0 + 8][i0] * w10 + sm.dotv[el0 + 8][i0 + 1] * w11;
                    }
                }
            }
#pragma unroll
            for (int mt = 0; mt < 2; ++mt)
#pragma unroll
                for (int rh = 0; rh < 2; ++rh) {
                    float v = pxs[mt][rh];
                    v += __shfl_xor_sync(0xffffffffu, v, 1);
                    v += __shfl_xor_sync(0xffffffffu, v, 2);
                    pxs[mt][rh] = v;
                    float u = pdot[mt][rh];
                    u += __shfl_xor_sync(0xffffffffu, u, 1);
                    u += __shfl_xor_sync(0xffffffffu, u, 2);
                    pdot[mt][rh] = u;
                }
            int j = lane & 3;
            float xsj = (j == 0) ? pxs[0][0] : (j == 1) ? pxs[0][1]
                      : (j == 2) ? pxs[1][0] : pxs[1][1];
            float dtj = (j == 0) ? pdot[0][0] : (j == 1) ? pdot[0][1]
                      : (j == 2) ? pdot[1][0] : pdot[1][1];
            int el = mb + (j >> 1) * 16 + (j & 1) * 8 + r;
            float out = fmaf(sm.sss[el], xsj, dtj);
            atomicAdd(g_accum + (size_t)sm.dst[el] * 96 + c, ALPHA * out);
        } else {
            int kk = c - 48;
            float t1[2][2] = {{0.f, 0.f}, {0.f, 0.f}};
            float tv[2][2][3];
#pragma unroll
            for (int mt = 0; mt < 2; ++mt)
#pragma unroll
                for (int rh = 0; rh < 2; ++rh)
#pragma unroll
                    for (int m = 0; m < 3; ++m) tv[mt][rh][m] = 0.f;
#pragma unroll
            for (int mt = 0; mt < 2; ++mt) {
                int el0 = mb + mt * 16 + r;
#pragma unroll
                for (int b = 0; b < 4; ++b) {
                    int g8 = h * 4 + b;
                    int q0 = g8 * 8 + q * 2;
                    float w00 = dlrelu(acc[mt][b][0]), w01 = dlrelu(acc[mt][b][1]);
                    float w10 = dlrelu(acc[mt][b][2]), w11 = dlrelu(acc[mt][b][3]);
                    if (g8 < 6) {
                        t1[mt][0] += sm.xs[el0][q0] * w00 + sm.xs[el0][q0 + 1] * w01;
                        t1[mt][1] += sm.xs[el0 + 8][q0] * w10 + sm.xs[el0 + 8][q0 + 1] * w11;
                    } else {
                        int i0 = q0 - 48;
#pragma unroll
                        for (int m = 0; m < 3; ++m) {
                            tv[mt][0][m] += sm.xv[el0][3 * i0 + m] * w00 +
                                            sm.xv[el0][3 * (i0 + 1) + m] * w01;
                            tv[mt][1][m] += sm.xv[el0 + 8][3 * i0 + m] * w10 +
                                            sm.xv[el0 + 8][3 * (i0 + 1) + m] * w11;
                        }
                    }
                }
            }
#pragma unroll
            for (int mt = 0; mt < 2; ++mt)
#pragma unroll
                for (int rh = 0; rh < 2; ++rh) {
                    float v = t1[mt][rh];
                    v += __shfl_xor_sync(0xffffffffu, v, 1);
                    v += __shfl_xor_sync(0xffffffffu, v, 2);
                    t1[mt][rh] = v;
#pragma unroll
                    for (int m = 0; m < 3; ++m) {
                        float u = tv[mt][rh][m];
                        u += __shfl_xor_sync(0xffffffffu, u, 1);
                        u += __shfl_xor_sync(0xffffffffu, u, 2);
                        tv[mt][rh][m] = u;
                    }
                }
            int j = lane & 3;
            float t1j = (j == 0) ? t1[0][0] : (j == 1) ? t1[0][1]
                      : (j == 2) ? t1[1][0] : t1[1][1];
            float tvj[3];
#pragma unroll
            for (int m = 0; m < 3; ++m)
                tvj[m] = (j == 0) ? tv[0][0][m] : (j == 1) ? tv[0][1][m]
                       : (j == 2) ? tv[1][0][m] : tv[1][1][m];
            int el = mb + (j >> 1) * 16 + (j & 1) * 8 + r;
            float ssv = sm.sss[el];
            float* base = g_accum + (size_t)sm.dst[el] * 96 + 48 + 3 * kk;
#pragma unroll
            for (int m = 0; m < 3; ++m)
                atomicAdd(base + m, ALPHA * fmaf(t1j, sm.sv[el][m], ssv * tvj[m]));
        }
    };

    prefetch(0, 0);
#pragma unroll 1
    for (int c2 = 0; c2 < 32; ++c2) {
        int ce = 2 * c2, co = ce + 1;
        // even chunk: buffer 0 -> accE ; epilogue of ce-1 (odd, accO)
        CP_WAIT0();
        __syncthreads();
        prefetch(co, 1);
        do_mma(0, accE);
        if (ce > 0) epilogue(ce - 1, accO);
        // odd chunk: buffer 1 -> accO ; epilogue of ce (even, accE)
        CP_WAIT0();
        __syncthreads();
        prefetch(co + 1, 0);
        do_mma(1, accO);
        epilogue(ce, accE);
    }
    epilogue(63, accO);
}

// ---------------- batchnorm statistics ----------------
__global__ __launch_bounds__(256) void k_stats(const float* __restrict__ bnw) {
    __shared__ float r1[256], r2[256];
    int b = blockIdx.x, t = threadIdx.x;
    float s1 = 0.f, s2 = 0.f;
    if (b < NSC) {
        for (int n = t; n < NNODES; n += 256) {
            float x = g_accum[(size_t)n * 96 + b];
            s1 += x;
            s2 += x * x;
        }
    } else {
        int k = b - NSC;
        for (int n = t; n < NNODES; n += 256) {
            const float* p = &g_accum[(size_t)n * 96 + 48 + 3 * k];
            s2 += p[0] * p[0] + p[1] * p[1] + p[2] * p[2];
        }
    }
    r1[t] = s1;
    r2[t] = s2;
    __syncthreads();
    for (int off = 128; off > 0; off >>= 1) {
        if (t < off) { r1[t] += r1[t + off]; r2[t] += r2[t + off]; }
        __syncthreads();
    }
    if (t == 0) {
        if (b < NSC) {
            float mean = r1[0] / (float)NNODES;
            float var = r2[0] / (float)NNODES - mean * mean;
            g_mean[b] = mean;
            g_rs[b] = rsqrtf(var + BN_EPS) * bnw[b];
        } else {
            int k = b - NSC;
            float vn = r2[0] / (3.0f * (float)NNODES);
            g_rsv[k] = rsqrtf(vn + BN_EPS) * bnw[NSC + k];
        }
    }
}

__global__ void k_final(const float* __restrict__ bnb, float* __restrict__ out) {
    int idx = blockIdx.x * 256 + threadIdx.x;
    if (idx >= NNODES * 96) return;
    int c = idx % 96;
    float x = g_accum[idx];
    float o;
    if (c < NSC) o = (x - g_mean[c]) * g_rs[c] + bnb[c];
    else         o = x * g_rsv[(c - 48) / 3];
    out[idx] = o;
}

// ---------------- launch ----------------
extern "C" void kernel_launch(void* const* d_in, const int* in_sizes, int n_in,
                              void* d_out, int out_size) {
    const float* node_attr = (const float*)d_in[0];
    const int* eidx_raw    = (const int*)d_in[1];
    const float* edge_attr = (const float*)d_in[2];
    const float* edge_sh   = (const float*)d_in[3];
    const float* fc_w1     = (const float*)d_in[4];
    const float* fc_b1     = (const float*)d_in[5];
    const float* fc_w2     = (const float*)d_in[6];
    const float* fc_b2     = (const float*)d_in[7];
    const float* bn_weight = (const float*)d_in[8];
    const float* bn_bias   = (const float*)d_in[9];
    float* out = (float*)d_out;

    cudaFuncSetAttribute(k_tp, cudaFuncAttributeMaxDynamicSharedMemorySize,
                         (int)sizeof(SmemT));

    k_detect_idx<<<1, 256>>>(eidx_raw);
    k_misc<<<(NNODES * 96 + 255) / 256, 256>>>(eidx_raw, node_attr);
    k_prep_frags<<<(NBF_TOTAL + NW1F + 255) / 256, 256>>>(fc_w2, fc_b2, fc_w1, fc_b1);
    k_tp<<<NEDGES / 64, 128, sizeof(SmemT)>>>(node_attr, edge_sh, edge_attr);
    k_stats<<<NSC + NVC, 256>>>(bn_weight);
    k_final<<<(NNODES * 96 + 255) / 256, 256>>>(bn_bias, out);
}

// round 11
// speedup vs baseline: 1.4745x; 1.4745x over previous
#include <cuda_runtime.h>
#include <cuda_fp16.h>
#include <stdint.h>

#define NNODES 4096
#define NEDGES 32768
#define NSC 48
#define NVC 16
#define NEF 128
#define WNUM 4096
#define BN_EPS 1e-5f
#define INV_SQRT3 0.57735026918962576f
#define ALPHA 0.125f

#define NCHUNKS 64
#define KSTEPS 9                              // 8 data ksteps (K=16) + 1 bias kstep
#define BFRAG_PER_CHUNK (KSTEPS * 8 * 32)     // uint2 entries = 2304
#define NBF_TOTAL (NCHUNKS * BFRAG_PER_CHUNK) // 147456
#define NW1F 4608                             // 9 ksteps * 16 n8 * 32 lanes

// ---------------- static device scratch ----------------
__device__ __align__(16) uint2 g_Bfrag[NBF_TOTAL]; // fp16 W2 fragment images
__device__ __align__(16) uint2 g_W1frag[NW1F];     // fp16 W1+b1 fragment images
__device__ float g_accum[NNODES * 96];
__device__ float g_mean[NSC];
__device__ float g_rs[NSC];
__device__ float g_rsv[NVC];
__device__ int g_src[NEDGES];
__device__ int g_dst[NEDGES];
__device__ int g_mode;

// ================= helpers =================
__device__ __forceinline__ uint32_t smem_u32(const void* p) {
    uint32_t a;
    asm("{ .reg .u64 t; cvta.to.shared.u64 t, %1; cvt.u32.u64 %0, t; }" : "=r"(a) : "l"(p));
    return a;
}
__device__ __forceinline__ void mma16(float* d, const uint32_t* a, uint32_t b0, uint32_t b1) {
    asm volatile(
        "mma.sync.aligned.m16n8k16.row.col.f32.f16.f16.f32 "
        "{%0,%1,%2,%3}, {%4,%5,%6,%7}, {%8,%9}, {%0,%1,%2,%3};\n"
        : "+f"(d[0]), "+f"(d[1]), "+f"(d[2]), "+f"(d[3])
        : "r"(a[0]), "r"(a[1]), "r"(a[2]), "r"(a[3]), "r"(b0), "r"(b1));
}
__device__ __forceinline__ void cpa16(uint32_t s, const void* g) {
    asm volatile("cp.async.ca.shared.global [%0], [%1], 16;" :: "r"(s), "l"(g));
}
#define CP_COMMIT() asm volatile("cp.async.commit_group;" ::: "memory")
#define CP_WAIT0()  asm volatile("cp.async.wait_group 0;" ::: "memory")

__device__ __forceinline__ float dlrelu(float x) { return (fabsf(x) <= 10.f) ? x : 0.01f * x; }
__device__ __forceinline__ uint32_t pack_relu(float a, float b) {
    __half2 h = __floats2half2_rn(fmaxf(a, 0.f), fmaxf(b, 0.f));
    return *reinterpret_cast<uint32_t*>(&h);
}

// column permutation: jp (permuted) -> original j of fc_w2
__device__ __forceinline__ int jorig_of(int jp) {
    int chunk = jp >> 6, q = jp & 63;
    if (chunk < 48) {
        return (q < 48) ? q * 48 + chunk : 2304 + (q - 48) * 48 + chunk;
    }
    int k = chunk - 48;
    return (q < 48) ? 3072 + q * 16 + k : 3840 + (q - 48) * 16 + k;
}

// ================= small prep kernels =================
__global__ void k_detect_idx(const int* __restrict__ raw) {
    __shared__ int flag;
    int t = threadIdx.x;
    if (t == 0) flag = 0;
    __syncthreads();
    for (int i = t; i < 2048; i += 256)
        if (raw[2 * i + 1] != 0) flag = 1;
    __syncthreads();
    if (t == 0) g_mode = flag;
}
// idx convert + accumulator init (merged)
__global__ void k_misc(const int* __restrict__ raw, const float* __restrict__ na) {
    int idx = blockIdx.x * 256 + threadIdx.x;
    if (idx < NEDGES) {
        if (g_mode) { g_src[idx] = raw[idx]; g_dst[idx] = raw[NEDGES + idx]; }
        else        { g_src[idx] = raw[2 * idx]; g_dst[idx] = raw[2 * (NEDGES + idx)]; }
    }
    if (idx < NNODES * 96) g_accum[idx] = na[idx];
}
// build fp16 fragment images for W2 (permuted, read directly from w2) and W1(+biases)
__global__ void k_prep_frags(const float* __restrict__ w2,
                             const float* __restrict__ b2,
                             const float* __restrict__ w1,
                             const float* __restrict__ b1) {
    int idx = blockIdx.x * 256 + threadIdx.x;
    if (idx < NBF_TOTAL) {
        int lane = idx & 31;
        int g8 = (idx >> 5) & 7;
        int rest = idx >> 8;        // chunk*9 + s
        int s = rest % KSTEPS, chunk = rest / KSTEPS;
        int q = g8 * 8 + (lane >> 2);
        int jo = jorig_of(chunk * 64 + q);
        int k0 = s * 16 + (lane & 3) * 2;
        float f[4];
#pragma unroll
        for (int r = 0; r < 4; ++r) {
            int k = k0 + (r >> 1) * 8 + (r & 1);
            f[r] = (k < 128) ? w2[(size_t)k * WNUM + jo] : ((k == 128) ? b2[jo] : 0.f);
        }
        uint2 out;
        __half2 h0 = __floats2half2_rn(f[0], f[1]);
        __half2 h1 = __floats2half2_rn(f[2], f[3]);
        out.x = *reinterpret_cast<uint32_t*>(&h0);
        out.y = *reinterpret_cast<uint32_t*>(&h1);
        g_Bfrag[idx] = out;
    } else if (idx < NBF_TOTAL + NW1F) {
        int v = idx - NBF_TOTAL;
        int lane = v & 31;
        int g = (v >> 5) & 15;
        int s = v >> 9;             // 0..8
        int col = g * 8 + (lane >> 2);
        int k0 = s * 16 + (lane & 3) * 2;
        float f[4];
#pragma unroll
        for (int r = 0; r < 4; ++r) {
            int k = k0 + (r >> 1) * 8 + (r & 1);
            f[r] = (k < 128) ? w1[k * 128 + col] : ((k == 128) ? b1[col] : 0.f);
        }
        uint2 out;
        __half2 h0 = __floats2half2_rn(f[0], f[1]);
        __half2 h1 = __floats2half2_rn(f[2], f[3]);
        out.x = *reinterpret_cast<uint32_t*>(&h0);
        out.y = *reinterpret_cast<uint32_t*>(&h1);
        g_W1frag[v] = out;
    }
}

// ================= fused stage-A + fp16 mma GEMM + tensor product + scatter =================
struct SmemT {
    uint2 B[2][BFRAG_PER_CHUNK];   // 36864 B — holds W1frag during prologue
    union {
        __half eah[64 * 144];      // 18432 B (prologue ea image)
        struct {
            __half2 xs2[64][25];   // 6400: xs pairs (q0,q0+1), stride 25 -> conflict-free
            __half2 xvp[64][25];   // 6400: [ip][m] = (xv[3*2ip+m], xv[3*(2ip+1)+m])
            __half2 dotv2[64][9];  // 2304: dot pairs
        } d;
    } u;
};   // total 55296 B -> 4 CTAs/SM

extern __shared__ __align__(16) char smemraw[];

__global__ __launch_bounds__(128, 4) void k_tp(const float* __restrict__ na,
                                               const float* __restrict__ sh,
                                               const float* __restrict__ ea) {
    SmemT& sm = *reinterpret_cast<SmemT*>(smemraw);
    int t = threadIdx.x, lane = t & 31, w = t >> 5;
    int h = w & 1;                 // n-half
    int mb = (w >> 1) * 32;        // m-block base (32 edges)
    int ebase = blockIdx.x * 64;
    int r = lane >> 2, q = lane & 3;
    uint32_t one = (q == 0) ? 0x00003c00u : 0u;   // half2(1, 0)

    // per-thread fixed output edge (used only at the final atomics)
    int j = lane & 3;
    int el_sel = mb + (j >> 1) * 16 + (j & 1) * 8 + r;
    float* arow;
    float sss_sel, sv_sel0, sv_sel1, sv_sel2;
    {
        int e = ebase + el_sel;
        arow = g_accum + (size_t)g_dst[e] * 96;
        float4 shv = __ldg(reinterpret_cast<const float4*>(sh) + e);
        sss_sel = shv.x; sv_sel0 = shv.y; sv_sel1 = shv.z; sv_sel2 = shv.w;
    }

    // ---- 1: stream W1 fragment images into the B double-buffer area ----
    {
        uint32_t sB = smem_u32(&sm.B[0][0]);
        const char* g = (const char*)g_W1frag;
#pragma unroll
        for (int i = 0; i < 18; ++i) cpa16(sB + (t + 128 * i) * 16, g + (t + 128 * i) * 16);
        CP_COMMIT();
    }
    // ---- 2: ea tile -> fp16 permuted smem image ----
    __half* eah = sm.u.eah;
    for (int i = t; i < 64 * 64; i += 128) {
        int e = i >> 6, c = (i & 63) * 2;
        float2 v = *reinterpret_cast<const float2*>(ea + (size_t)(ebase + e) * 128 + c);
        int s = c >> 4, ww = c & 15;
        int pos = ((ww & 7) >> 1) * 4 + ((ww >> 3) << 1);
        __half2 hp = __floats2half2_rn(v.x, v.y);
        *reinterpret_cast<__half2*>(eah + e * 144 + s * 16 + pos) = hp;
    }
    CP_WAIT0();
    __syncthreads();

    // ---- 3: prologue MMA — compute H fragments (A frags for main loop) ----
    uint32_t afr[2][8][4];
    const uint2* w1f = reinterpret_cast<const uint2*>(&sm.B[0][0]);
#pragma unroll
    for (int mt = 0; mt < 2; ++mt) {
        float accH[16][4];
#pragma unroll
        for (int g = 0; g < 16; ++g)
            accH[g][0] = accH[g][1] = accH[g][2] = accH[g][3] = 0.f;
        const __half* row0 = eah + (mb + mt * 16 + r) * 144;
        const __half* row8 = row0 + 8 * 144;
#pragma unroll 1
        for (int s = 0; s < KSTEPS; ++s) {
            uint32_t af[4];
            if (s < 8) {
                uint2 ae0 = *reinterpret_cast<const uint2*>(row0 + s * 16 + q * 4);
                uint2 ae1 = *reinterpret_cast<const uint2*>(row8 + s * 16 + q * 4);
                af[0] = ae0.x; af[1] = ae1.x; af[2] = ae0.y; af[3] = ae1.y;
            } else {
                af[0] = one; af[1] = one; af[2] = 0u; af[3] = 0u;
            }
#pragma unroll
            for (int g = 0; g < 16; ++g) {
                uint2 bf = w1f[(s * 16 + g) * 32 + lane];
                mma16(accH[g], af, bf.x, bf.y);
            }
        }
#pragma unroll
        for (int sp = 0; sp < 8; ++sp) {
            afr[mt][sp][0] = pack_relu(accH[2 * sp][0], accH[2 * sp][1]);
            afr[mt][sp][1] = pack_relu(accH[2 * sp][2], accH[2 * sp][3]);
            afr[mt][sp][2] = pack_relu(accH[2 * sp + 1][0], accH[2 * sp + 1][1]);
            afr[mt][sp][3] = pack_relu(accH[2 * sp + 1][2], accH[2 * sp + 1][3]);
        }
    }
    __syncthreads();   // all warps done reading W1frag / ea_h

    // ---- 4: start B pipeline (chunk 0 -> buf 0) ----
    {
        uint32_t sB = smem_u32(&sm.B[0][0]);
        const char* g = (const char*)g_Bfrag;
#pragma unroll
        for (int i = 0; i < 9; ++i) cpa16(sB + (t + 128 * i) * 16, g + (t + 128 * i) * 16);
        CP_COMMIT();
    }
    // ---- 5: per-edge node data -> fp16 packed tables (overwrites dead ea image) ----
    if (t < 64) {
        int e = ebase + t;
        float4 shv = __ldg(reinterpret_cast<const float4*>(sh) + e);
        __half* xsh = reinterpret_cast<__half*>(&sm.u.d.xs2[t][0]);
        __half* xvh = reinterpret_cast<__half*>(&sm.u.d.xvp[t][0]);
        __half* dth = reinterpret_cast<__half*>(&sm.u.d.dotv2[t][0]);
        const float4* nr = reinterpret_cast<const float4*>(na + (size_t)g_src[e] * 96);
        float dac[16];
#pragma unroll
        for (int i = 0; i < 16; ++i) dac[i] = 0.f;
        float svm[3] = {shv.y, shv.z, shv.w};
#pragma unroll
        for (int qq = 0; qq < 24; ++qq) {
            float4 v = __ldg(nr + qq);
            float vv[4] = {v.x, v.y, v.z, v.w};
#pragma unroll
            for (int jj = 0; jj < 4; ++jj) {
                int c = qq * 4 + jj;
                if (c < 48) {
                    xsh[c] = __float2half(vv[jj]);
                } else {
                    int d = c - 48;
                    int i = d / 3, m = d % 3;
                    dac[i] += vv[jj] * svm[m];
                    // dup pair layout: half index = (ip*3+m)*2 + (i&1)
                    xvh[((i >> 1) * 3 + m) * 2 + (i & 1)] = __float2half(vv[jj]);
                }
            }
        }
#pragma unroll
        for (int i = 0; i < 16; ++i)
            dth[i] = __float2half(INV_SQRT3 * dac[i]);
    }

    // ---- 6: main loop (in-order, single accumulator set) ----
#pragma unroll 1
    for (int c = 0; c < NCHUNKS; ++c) {
        int p = c & 1;
        CP_WAIT0();
        __syncthreads();
        if (c + 1 < NCHUNKS) {
            uint32_t sB = smem_u32(&sm.B[1 - p][0]);
            const char* g = (const char*)(g_Bfrag + (size_t)(c + 1) * BFRAG_PER_CHUNK);
#pragma unroll
            for (int i = 0; i < 9; ++i) cpa16(sB + (t + 128 * i) * 16, g + (t + 128 * i) * 16);
        }
        CP_COMMIT();
        // ---- MMA: m32 x n32 per warp, K=144 ----
        float acc[2][4][4];
#pragma unroll
        for (int mt = 0; mt < 2; ++mt)
#pragma unroll
            for (int b = 0; b < 4; ++b)
#pragma unroll
                for (int rr = 0; rr < 4; ++rr) acc[mt][b][rr] = 0.f;
#pragma unroll
        for (int s = 0; s < 8; ++s) {
#pragma unroll
            for (int b = 0; b < 4; ++b) {
                uint2 bf = sm.B[p][(s * 8 + h * 4 + b) * 32 + lane];
                mma16(acc[0][b], afr[0][s], bf.x, bf.y);
                mma16(acc[1][b], afr[1][s], bf.x, bf.y);
            }
        }
        {
            uint32_t af1[4] = {one, one, 0u, 0u};
#pragma unroll
            for (int b = 0; b < 4; ++b) {
                uint2 bf = sm.B[p][(8 * 8 + h * 4 + b) * 32 + lane];
                mma16(acc[0][b], af1, bf.x, bf.y);
                mma16(acc[1][b], af1, bf.x, bf.y);
            }
        }
        // ---- epilogue (same chunk) ----
        if (c < 48) {
            float pxs[2][2] = {{0.f, 0.f}, {0.f, 0.f}};
            float pdot[2][2] = {{0.f, 0.f}, {0.f, 0.f}};
#pragma unroll
            for (int mt = 0; mt < 2; ++mt) {
                int el0 = mb + mt * 16 + r;
#pragma unroll
                for (int b = 0; b < 4; ++b) {
                    int g8 = h * 4 + b;
                    float w00 = dlrelu(acc[mt][b][0]), w01 = dlrelu(acc[mt][b][1]);
                    float w10 = dlrelu(acc[mt][b][2]), w11 = dlrelu(acc[mt][b][3]);
                    if (g8 < 6) {
                        float2 x0 = __half22float2(sm.u.d.xs2[el0][g8 * 4 + q]);
                        float2 x1 = __half22float2(sm.u.d.xs2[el0 + 8][g8 * 4 + q]);
                        pxs[mt][0] += x0.x * w00 + x0.y * w01;
                        pxs[mt][1] += x1.x * w10 + x1.y * w11;
                    } else {
                        float2 d0 = __half22float2(sm.u.d.dotv2[el0][(g8 - 6) * 4 + q]);
                        float2 d1 = __half22float2(sm.u.d.dotv2[el0 + 8][(g8 - 6) * 4 + q]);
                        pdot[mt][0] += d0.x * w00 + d0.y * w01;
                        pdot[mt][1] += d1.x * w10 + d1.y * w11;
                    }
                }
            }
#pragma unroll
            for (int mt = 0; mt < 2; ++mt)
#pragma unroll
                for (int rh = 0; rh < 2; ++rh) {
                    float v = pxs[mt][rh];
                    v += __shfl_xor_sync(0xffffffffu, v, 1);
                    v += __shfl_xor_sync(0xffffffffu, v, 2);
                    pxs[mt][rh] = v;
                    float u2 = pdot[mt][rh];
                    u2 += __shfl_xor_sync(0xffffffffu, u2, 1);
                    u2 += __shfl_xor_sync(0xffffffffu, u2, 2);
                    pdot[mt][rh] = u2;
                }
            float xsj = (j == 0) ? pxs[0][0] : (j == 1) ? pxs[0][1]
                      : (j == 2) ? pxs[1][0] : pxs[1][1];
            float dtj = (j == 0) ? pdot[0][0] : (j == 1) ? pdot[0][1]
                      : (j == 2) ? pdot[1][0] : pdot[1][1];
            atomicAdd(arow + c, ALPHA * fmaf(sss_sel, xsj, dtj));
        } else {
            int kk = c - 48;
            float t1[2][2] = {{0.f, 0.f}, {0.f, 0.f}};
            float tv[2][2][3];
#pragma unroll
            for (int mt = 0; mt < 2; ++mt)
#pragma unroll
                for (int rh = 0; rh < 2; ++rh)
#pragma unroll
                    for (int m = 0; m < 3; ++m) tv[mt][rh][m] = 0.f;
#pragma unroll
            for (int mt = 0; mt < 2; ++mt) {
                int el0 = mb + mt * 16 + r;
#pragma unroll
                for (int b = 0; b < 4; ++b) {
                    int g8 = h * 4 + b;
                    float w00 = dlrelu(acc[mt][b][0]), w01 = dlrelu(acc[mt][b][1]);
                    float w10 = dlrelu(acc[mt][b][2]), w11 = dlrelu(acc[mt][b][3]);
                    if (g8 < 6) {
                        float2 x0 = __half22float2(sm.u.d.xs2[el0][g8 * 4 + q]);
                        float2 x1 = __half22float2(sm.u.d.xs2[el0 + 8][g8 * 4 + q]);
                        t1[mt][0] += x0.x * w00 + x0.y * w01;
                        t1[mt][1] += x1.x * w10 + x1.y * w11;
                    } else {
                        int ip = (g8 - 6) * 4 + q;
#pragma unroll
                        for (int m = 0; m < 3; ++m) {
                            float2 v0 = __half22float2(sm.u.d.xvp[el0][ip * 3 + m]);
                            float2 v1 = __half22float2(sm.u.d.xvp[el0 + 8][ip * 3 + m]);
                            tv[mt][0][m] += v0.x * w00 + v0.y * w01;
                            tv[mt][1][m] += v1.x * w10 + v1.y * w11;
                        }
                    }
                }
            }
#pragma unroll
            for (int mt = 0; mt < 2; ++mt)
#pragma unroll
                for (int rh = 0; rh < 2; ++rh) {
                    float v = t1[mt][rh];
                    v += __shfl_xor_sync(0xffffffffu, v, 1);
                    v += __shfl_xor_sync(0xffffffffu, v, 2);
                    t1[mt][rh] = v;
#pragma unroll
                    for (int m = 0; m < 3; ++m) {
                        float u2 = tv[mt][rh][m];
                        u2 += __shfl_xor_sync(0xffffffffu, u2, 1);
                        u2 += __shfl_xor_sync(0xffffffffu, u2, 2);
                        tv[mt][rh][m] = u2;
                    }
                }
            float t1j = (j == 0) ? t1[0][0] : (j == 1) ? t1[0][1]
                      : (j == 2) ? t1[1][0] : t1[1][1];
            float tvj[3];
#pragma unroll
            for (int m = 0; m < 3; ++m)
                tvj[m] = (j == 0) ? tv[0][0][m] : (j == 1) ? tv[0][1][m]
                       : (j == 2) ? tv[1][0][m] : tv[1][1][m];
            float* base = arow + 48 + 3 * kk;
            atomicAdd(base + 0, ALPHA * fmaf(t1j, sv_sel0, sss_sel * tvj[0]));
            atomicAdd(base + 1, ALPHA * fmaf(t1j, sv_sel1, sss_sel * tvj[1]));
            atomicAdd(base + 2, ALPHA * fmaf(t1j, sv_sel2, sss_sel * tvj[2]));
        }
    }
}

// ---------------- batchnorm statistics ----------------
__global__ __launch_bounds__(256) void k_stats(const float* __restrict__ bnw) {
    __shared__ float r1[256], r2[256];
    int b = blockIdx.x, t = threadIdx.x;
    float s1 = 0.f, s2 = 0.f;
    if (b < NSC) {
        for (int n = t; n < NNODES; n += 256) {
            float x = g_accum[(size_t)n * 96 + b];
            s1 += x;
            s2 += x * x;
        }
    } else {
        int k = b - NSC;
        for (int n = t; n < NNODES; n += 256) {
            const float* p = &g_accum[(size_t)n * 96 + 48 + 3 * k];
            s2 += p[0] * p[0] + p[1] * p[1] + p[2] * p[2];
        }
    }
    r1[t] = s1;
    r2[t] = s2;
    __syncthreads();
    for (int off = 128; off > 0; off >>= 1) {
        if (t < off) { r1[t] += r1[t + off]; r2[t] += r2[t + off]; }
        __syncthreads();
    }
    if (t == 0) {
        if (b < NSC) {
            float mean = r1[0] / (float)NNODES;
            float var = r2[0] / (float)NNODES - mean * mean;
            g_mean[b] = mean;
            g_rs[b] = rsqrtf(var + BN_EPS) * bnw[b];
        } else {
            int k = b - NSC;
            float vn = r2[0] / (3.0f * (float)NNODES);
            g_rsv[k] = rsqrtf(vn + BN_EPS) * bnw[NSC + k];
        }
    }
}

__global__ void k_final(const float* __restrict__ bnb, float* __restrict__ out) {
    int idx = blockIdx.x * 256 + threadIdx.x;
    if (idx >= NNODES * 96) return;
    int c = idx % 96;
    float x = g_accum[idx];
    float o;
    if (c < NSC) o = (x - g_mean[c]) * g_rs[c] + bnb[c];
    else         o = x * g_rsv[(c - 48) / 3];
    out[idx] = o;
}

// ---------------- launch ----------------
extern "C" void kernel_launch(void* const* d_in, const int* in_sizes, int n_in,
                              void* d_out, int out_size) {
    const float* node_attr = (const float*)d_in[0];
    const int* eidx_raw    = (const int*)d_in[1];
    const float* edge_attr = (const float*)d_in[2];
    const float* edge_sh   = (const float*)d_in[3];
    const float* fc_w1     = (const float*)d_in[4];
    const float* fc_b1     = (const float*)d_in[5];
    const float* fc_w2     = (const float*)d_in[6];
    const float* fc_b2     = (const float*)d_in[7];
    const float* bn_weight = (const float*)d_in[8];
    const float* bn_bias   = (const float*)d_in[9];
    float* out = (float*)d_out;

    cudaFuncSetAttribute(k_tp, cudaFuncAttributeMaxDynamicSharedMemorySize,
                         (int)sizeof(SmemT));

    k_detect_idx<<<1, 256>>>(eidx_raw);
    k_misc<<<(NNODES * 96 + 255) / 256, 256>>>(eidx_raw, node_attr);
    k_prep_frags<<<(NBF_TOTAL + NW1F + 255) / 256, 256>>>(fc_w2, fc_b2, fc_w1, fc_b1);
    k_tp<<<NEDGES / 64, 128, sizeof(SmemT)>>>(node_attr, edge_sh, edge_attr);
    k_stats<<<NSC + NVC, 256>>>(bn_weight);
    k_final<<<(NNODES * 96 + 255) / 256, 256>>>(bn_bias, out);
}

// round 12
// speedup vs baseline: 1.5485x; 1.0502x over previous
#include <cuda_runtime.h>
#include <cuda_fp16.h>
#include <stdint.h>

#define NNODES 4096
#define NEDGES 32768
#define NSC 48
#define NVC 16
#define NEF 128
#define WNUM 4096
#define BN_EPS 1e-5f
#define INV_SQRT3 0.57735026918962576f
#define ALPHA 0.125f

#define NCHUNKS 64
#define KS 8                                  // 8 data ksteps (K=16 each), bias in epilogue
#define BFRAG_PER_CHUNK (KS * 8 * 32)         // uint2 entries = 2048
#define NBF_TOTAL (NCHUNKS * BFRAG_PER_CHUNK) // 131072
#define NW1F 4096                             // 8 ksteps * 16 n8 * 32 lanes
#define NBIAS 2048                            // 64 chunks * 32 half2

// ---------------- static device scratch ----------------
__device__ __align__(16) uint2 g_Bfrag[NBF_TOTAL]; // fp16 W2 fragment images (permuted)
__device__ __align__(16) uint2 g_W1frag[NW1F];     // fp16 W1 fragment images
__device__ __align__(16) uint32_t g_b2h[NBIAS];    // permuted fc_b2, half2 pairs
__device__ float g_accum[NNODES * 96];
__device__ float g_mean[NSC];
__device__ float g_rs[NSC];
__device__ float g_rsv[NVC];
__device__ int g_src[NEDGES];
__device__ int g_dst[NEDGES];
__device__ int g_mode;

// ================= helpers =================
__device__ __forceinline__ uint32_t smem_u32(const void* p) {
    uint32_t a;
    asm("{ .reg .u64 t; cvta.to.shared.u64 t, %1; cvt.u32.u64 %0, t; }" : "=r"(a) : "l"(p));
    return a;
}
__device__ __forceinline__ void mma16(float* d, const uint32_t* a, uint32_t b0, uint32_t b1) {
    asm volatile(
        "mma.sync.aligned.m16n8k16.row.col.f32.f16.f16.f32 "
        "{%0,%1,%2,%3}, {%4,%5,%6,%7}, {%8,%9}, {%0,%1,%2,%3};\n"
        : "+f"(d[0]), "+f"(d[1]), "+f"(d[2]), "+f"(d[3])
        : "r"(a[0]), "r"(a[1]), "r"(a[2]), "r"(a[3]), "r"(b0), "r"(b1));
}
__device__ __forceinline__ void cpa16(uint32_t s, const void* g) {
    asm volatile("cp.async.ca.shared.global [%0], [%1], 16;" :: "r"(s), "l"(g));
}
#define CP_COMMIT() asm volatile("cp.async.commit_group;" ::: "memory")
#define CP_WAIT0()  asm volatile("cp.async.wait_group 0;" ::: "memory")

__device__ __forceinline__ float dlrelu(float x) { return (fabsf(x) <= 10.f) ? x : 0.01f * x; }
__device__ __forceinline__ uint32_t pack_relu(float a, float b) {
    __half2 h = __floats2half2_rn(fmaxf(a, 0.f), fmaxf(b, 0.f));
    return *reinterpret_cast<uint32_t*>(&h);
}

// column permutation: jp (permuted) -> original j of fc_w2
__device__ __forceinline__ int jorig_of(int jp) {
    int chunk = jp >> 6, q = jp & 63;
    if (chunk < 48) {
        return (q < 48) ? q * 48 + chunk : 2304 + (q - 48) * 48 + chunk;
    }
    int k = chunk - 48;
    return (q < 48) ? 3072 + q * 16 + k : 3840 + (q - 48) * 16 + k;
}

// ================= small prep kernels =================
__global__ void k_detect_idx(const int* __restrict__ raw) {
    __shared__ int flag;
    int t = threadIdx.x;
    if (t == 0) flag = 0;
    __syncthreads();
    for (int i = t; i < 2048; i += 256)
        if (raw[2 * i + 1] != 0) flag = 1;
    __syncthreads();
    if (t == 0) g_mode = flag;
}
// idx convert + accumulator init (merged)
__global__ void k_misc(const int* __restrict__ raw, const float* __restrict__ na) {
    int idx = blockIdx.x * 256 + threadIdx.x;
    if (idx < NEDGES) {
        if (g_mode) { g_src[idx] = raw[idx]; g_dst[idx] = raw[NEDGES + idx]; }
        else        { g_src[idx] = raw[2 * idx]; g_dst[idx] = raw[2 * (NEDGES + idx)]; }
    }
    if (idx < NNODES * 96) g_accum[idx] = na[idx];
}
// build fp16 fragment images: W2 (permuted), W1, permuted b2 table
__global__ void k_prep_frags(const float* __restrict__ w2,
                             const float* __restrict__ b2,
                             const float* __restrict__ w1) {
    int idx = blockIdx.x * 256 + threadIdx.x;
    if (idx < NBF_TOTAL) {
        int lane = idx & 31;
        int g8 = (idx >> 5) & 7;
        int rest = idx >> 8;        // chunk*8 + s
        int s = rest & 7, chunk = rest >> 3;
        int q = g8 * 8 + (lane >> 2);
        int jo = jorig_of(chunk * 64 + q);
        int k0 = s * 16 + (lane & 3) * 2;
        float f[4];
#pragma unroll
        for (int r = 0; r < 4; ++r) {
            int k = k0 + (r >> 1) * 8 + (r & 1);
            f[r] = w2[(size_t)k * WNUM + jo];
        }
        uint2 out;
        __half2 h0 = __floats2half2_rn(f[0], f[1]);
        __half2 h1 = __floats2half2_rn(f[2], f[3]);
        out.x = *reinterpret_cast<uint32_t*>(&h0);
        out.y = *reinterpret_cast<uint32_t*>(&h1);
        g_Bfrag[idx] = out;
    } else if (idx < NBF_TOTAL + NW1F) {
        int v = idx - NBF_TOTAL;
        int lane = v & 31;
        int g = (v >> 5) & 15;
        int s = v >> 9;             // 0..7
        int col = g * 8 + (lane >> 2);
        int k0 = s * 16 + (lane & 3) * 2;
        float f[4];
#pragma unroll
        for (int r = 0; r < 4; ++r) {
            int k = k0 + (r >> 1) * 8 + (r & 1);
            f[r] = w1[k * 128 + col];
        }
        uint2 out;
        __half2 h0 = __floats2half2_rn(f[0], f[1]);
        __half2 h1 = __floats2half2_rn(f[2], f[3]);
        out.x = *reinterpret_cast<uint32_t*>(&h0);
        out.y = *reinterpret_cast<uint32_t*>(&h1);
        g_W1frag[v] = out;
    } else if (idx < NBF_TOTAL + NW1F + NBIAS) {
        int v = idx - NBF_TOTAL - NW1F;
        int c = v >> 5, i = v & 31;
        int g8 = i >> 2, q = i & 3;
        int q0 = g8 * 8 + q * 2;
        __half2 h = __floats2half2_rn(b2[jorig_of(c * 64 + q0)],
                                      b2[jorig_of(c * 64 + q0 + 1)]);
        g_b2h[v] = *reinterpret_cast<uint32_t*>(&h);
    }
}

// ================= fused stage-A + fp16 mma GEMM + tensor product + scatter =================
struct SmemT {
    uint2 B[2][BFRAG_PER_CHUNK];   // 32768 B — holds W1frag during prologue
    union {
        __half eah[64 * 144];      // 18432 B (prologue ea image)
        struct {
            __half2 xs2[64][25];   // 6400
            __half2 xvp[64][25];   // 6400
            __half2 dotv2[64][9];  // 2304
            uint32_t bias[NBIAS];  // 8192 (permuted b2, half2 pairs)
        } d;                       // 23296
    } u;
};   // total 56064 B -> 4 CTAs/SM

extern __shared__ __align__(16) char smemraw[];

__global__ __launch_bounds__(128, 4) void k_tp(const float* __restrict__ na,
                                               const float* __restrict__ sh,
                                               const float* __restrict__ ea,
                                               const float* __restrict__ b1) {
    SmemT& sm = *reinterpret_cast<SmemT*>(smemraw);
    int t = threadIdx.x, lane = t & 31, w = t >> 5;
    int h = w & 1;                 // n-half
    int mb = (w >> 1) * 32;        // m-block base (32 edges)
    int ebase = blockIdx.x * 64;
    int r = lane >> 2, q = lane & 3;

    // per-thread fixed output edge (used only at the final atomics)
    int j = lane & 3;
    int el_sel = mb + (j >> 1) * 16 + (j & 1) * 8 + r;
    float* arow;
    float sss_sel, sv_sel0, sv_sel1, sv_sel2;
    {
        int e = ebase + el_sel;
        arow = g_accum + (size_t)g_dst[e] * 96;
        float4 shv = __ldg(reinterpret_cast<const float4*>(sh) + e);
        sss_sel = shv.x; sv_sel0 = shv.y; sv_sel1 = shv.z; sv_sel2 = shv.w;
    }

    // ---- 1: stream W1 fragment images into the B double-buffer area (32 KB) ----
    {
        uint32_t sB = smem_u32(&sm.B[0][0]);
        const char* g = (const char*)g_W1frag;
#pragma unroll
        for (int i = 0; i < 16; ++i) cpa16(sB + (t + 128 * i) * 16, g + (t + 128 * i) * 16);
        CP_COMMIT();
    }
    // ---- 2: ea tile -> fp16 permuted smem image ----
    __half* eah = sm.u.eah;
    for (int i = t; i < 64 * 64; i += 128) {
        int e = i >> 6, c = (i & 63) * 2;
        float2 v = *reinterpret_cast<const float2*>(ea + (size_t)(ebase + e) * 128 + c);
        int s = c >> 4, ww = c & 15;
        int pos = ((ww & 7) >> 1) * 4 + ((ww >> 3) << 1);
        __half2 hp = __floats2half2_rn(v.x, v.y);
        *reinterpret_cast<__half2*>(eah + e * 144 + s * 16 + pos) = hp;
    }
    CP_WAIT0();
    __syncthreads();

    // ---- 3: prologue MMA — compute H fragments; b1 folded into acc init ----
    uint32_t afr[2][KS][4];
    const uint2* w1f = reinterpret_cast<const uint2*>(&sm.B[0][0]);
    const float2* b1f2 = reinterpret_cast<const float2*>(b1);
#pragma unroll
    for (int mt = 0; mt < 2; ++mt) {
        float accH[16][4];
#pragma unroll
        for (int g = 0; g < 16; ++g) {
            float2 bv = __ldg(&b1f2[g * 4 + q]);
            accH[g][0] = bv.x; accH[g][1] = bv.y;
            accH[g][2] = bv.x; accH[g][3] = bv.y;
        }
        const __half* row0 = eah + (mb + mt * 16 + r) * 144;
        const __half* row8 = row0 + 8 * 144;
#pragma unroll 1
        for (int s = 0; s < KS; ++s) {
            uint2 ae0 = *reinterpret_cast<const uint2*>(row0 + s * 16 + q * 4);
            uint2 ae1 = *reinterpret_cast<const uint2*>(row8 + s * 16 + q * 4);
            uint32_t af[4] = {ae0.x, ae1.x, ae0.y, ae1.y};
#pragma unroll
            for (int g = 0; g < 16; ++g) {
                uint2 bf = w1f[(s * 16 + g) * 32 + lane];
                mma16(accH[g], af, bf.x, bf.y);
            }
        }
#pragma unroll
        for (int sp = 0; sp < KS; ++sp) {
            afr[mt][sp][0] = pack_relu(accH[2 * sp][0], accH[2 * sp][1]);
            afr[mt][sp][1] = pack_relu(accH[2 * sp][2], accH[2 * sp][3]);
            afr[mt][sp][2] = pack_relu(accH[2 * sp + 1][0], accH[2 * sp + 1][1]);
            afr[mt][sp][3] = pack_relu(accH[2 * sp + 1][2], accH[2 * sp + 1][3]);
        }
    }
    __syncthreads();   // all warps done reading W1frag / ea_h

    // ---- 4: start B pipeline (chunk 0 -> buf 0) + bias table ----
    {
        uint32_t sB = smem_u32(&sm.B[0][0]);
        const char* g = (const char*)g_Bfrag;
#pragma unroll
        for (int i = 0; i < 8; ++i) cpa16(sB + (t + 128 * i) * 16, g + (t + 128 * i) * 16);
        uint32_t sBias = smem_u32(&sm.u.d.bias[0]);
        const char* gb = (const char*)g_b2h;
#pragma unroll
        for (int i = 0; i < 4; ++i) cpa16(sBias + (t + 128 * i) * 16, gb + (t + 128 * i) * 16);
        CP_COMMIT();
    }
    // ---- 5: per-edge node data -> fp16 packed tables (overwrites dead ea image) ----
    if (t < 64) {
        int e = ebase + t;
        float4 shv = __ldg(reinterpret_cast<const float4*>(sh) + e);
        __half* xsh = reinterpret_cast<__half*>(&sm.u.d.xs2[t][0]);
        __half* xvh = reinterpret_cast<__half*>(&sm.u.d.xvp[t][0]);
        __half* dth = reinterpret_cast<__half*>(&sm.u.d.dotv2[t][0]);
        const float4* nr = reinterpret_cast<const float4*>(na + (size_t)g_src[e] * 96);
        float dac[16];
#pragma unroll
        for (int i = 0; i < 16; ++i) dac[i] = 0.f;
        float svm[3] = {shv.y, shv.z, shv.w};
#pragma unroll
        for (int qq = 0; qq < 24; ++qq) {
            float4 v = __ldg(nr + qq);
            float vv[4] = {v.x, v.y, v.z, v.w};
#pragma unroll
            for (int jj = 0; jj < 4; ++jj) {
                int c = qq * 4 + jj;
                if (c < 48) {
                    xsh[c] = __float2half(vv[jj]);
                } else {
                    int d = c - 48;
                    int i = d / 3, m = d % 3;
                    dac[i] += vv[jj] * svm[m];
                    xvh[((i >> 1) * 3 + m) * 2 + (i & 1)] = __float2half(vv[jj]);
                }
            }
        }
#pragma unroll
        for (int i = 0; i < 16; ++i)
            dth[i] = __float2half(INV_SQRT3 * dac[i]);
    }

    // ---- 6: main loop ----
#pragma unroll 1
    for (int c = 0; c < NCHUNKS; ++c) {
        int p = c & 1;
        CP_WAIT0();
        __syncthreads();
        if (c + 1 < NCHUNKS) {
            uint32_t sB = smem_u32(&sm.B[1 - p][0]);
            const char* g = (const char*)(g_Bfrag + (size_t)(c + 1) * BFRAG_PER_CHUNK);
#pragma unroll
            for (int i = 0; i < 8; ++i) cpa16(sB + (t + 128 * i) * 16, g + (t + 128 * i) * 16);
        }
        CP_COMMIT();
        // ---- MMA: m32 x n32 per warp, K=128 ----
        float acc[2][4][4];
#pragma unroll
        for (int mt = 0; mt < 2; ++mt)
#pragma unroll
            for (int b = 0; b < 4; ++b)
#pragma unroll
                for (int rr = 0; rr < 4; ++rr) acc[mt][b][rr] = 0.f;
#pragma unroll
        for (int s = 0; s < KS; ++s) {
#pragma unroll
            for (int b = 0; b < 4; ++b) {
                uint2 bf = sm.B[p][(s * 8 + h * 4 + b) * 32 + lane];
                mma16(acc[0][b], afr[0][s], bf.x, bf.y);
                mma16(acc[1][b], afr[1][s], bf.x, bf.y);
            }
        }
        // ---- epilogue (bias added here) ----
        float2 bb[4];
#pragma unroll
        for (int b = 0; b < 4; ++b)
            bb[b] = __half22float2(*reinterpret_cast<const __half2*>(
                &sm.u.d.bias[c * 32 + (h * 4 + b) * 4 + q]));
        if (c < 48) {
            float pxs[2][2] = {{0.f, 0.f}, {0.f, 0.f}};
            float pdot[2][2] = {{0.f, 0.f}, {0.f, 0.f}};
#pragma unroll
            for (int mt = 0; mt < 2; ++mt) {
                int el0 = mb + mt * 16 + r;
#pragma unroll
                for (int b = 0; b < 4; ++b) {
                    int g8 = h * 4 + b;
                    float w00 = dlrelu(acc[mt][b][0] + bb[b].x), w01 = dlrelu(acc[mt][b][1] + bb[b].y);
                    float w10 = dlrelu(acc[mt][b][2] + bb[b].x), w11 = dlrelu(acc[mt][b][3] + bb[b].y);
                    if (g8 < 6) {
                        float2 x0 = __half22float2(sm.u.d.xs2[el0][g8 * 4 + q]);
                        float2 x1 = __half22float2(sm.u.d.xs2[el0 + 8][g8 * 4 + q]);
                        pxs[mt][0] += x0.x * w00 + x0.y * w01;
                        pxs[mt][1] += x1.x * w10 + x1.y * w11;
                    } else {
                        float2 d0 = __half22float2(sm.u.d.dotv2[el0][(g8 - 6) * 4 + q]);
                        float2 d1 = __half22float2(sm.u.d.dotv2[el0 + 8][(g8 - 6) * 4 + q]);
                        pdot[mt][0] += d0.x * w00 + d0.y * w01;
                        pdot[mt][1] += d1.x * w10 + d1.y * w11;
                    }
                }
            }
#pragma unroll
            for (int mt = 0; mt < 2; ++mt)
#pragma unroll
                for (int rh = 0; rh < 2; ++rh) {
                    float v = pxs[mt][rh];
                    v += __shfl_xor_sync(0xffffffffu, v, 1);
                    v += __shfl_xor_sync(0xffffffffu, v, 2);
                    pxs[mt][rh] = v;
                    float u2 = pdot[mt][rh];
                    u2 += __shfl_xor_sync(0xffffffffu, u2, 1);
                    u2 += __shfl_xor_sync(0xffffffffu, u2, 2);
                    pdot[mt][rh] = u2;
                }
            float xsj = (j == 0) ? pxs[0][0] : (j == 1) ? pxs[0][1]
                      : (j == 2) ? pxs[1][0] : pxs[1][1];
            float dtj = (j == 0) ? pdot[0][0] : (j == 1) ? pdot[0][1]
                      : (j == 2) ? pdot[1][0] : pdot[1][1];
            atomicAdd(arow + c, ALPHA * fmaf(sss_sel, xsj, dtj));
        } else {
            int kk = c - 48;
            float t1[2][2] = {{0.f, 0.f}, {0.f, 0.f}};
            float tv[2][2][3];
#pragma unroll
            for (int mt = 0; mt < 2; ++mt)
#pragma unroll
                for (int rh = 0; rh < 2; ++rh)
#pragma unroll
                    for (int m = 0; m < 3; ++m) tv[mt][rh][m] = 0.f;
#pragma unroll
            for (int mt = 0; mt < 2; ++mt) {
                int el0 = mb + mt * 16 + r;
#pragma unroll
                for (int b = 0; b < 4; ++b) {
                    int g8 = h * 4 + b;
                    float w00 = dlrelu(acc[mt][b][0] + bb[b].x), w01 = dlrelu(acc[mt][b][1] + bb[b].y);
                    float w10 = dlrelu(acc[mt][b][2] + bb[b].x), w11 = dlrelu(acc[mt][b][3] + bb[b].y);
                    if (g8 < 6) {
                        float2 x0 = __half22float2(sm.u.d.xs2[el0][g8 * 4 + q]);
                        float2 x1 = __half22float2(sm.u.d.xs2[el0 + 8][g8 * 4 + q]);
                        t1[mt][0] += x0.x * w00 + x0.y * w01;
                        t1[mt][1] += x1.x * w10 + x1.y * w11;
                    } else {
                        int ip = (g8 - 6) * 4 + q;
#pragma unroll
                        for (int m = 0; m < 3; ++m) {
                            float2 v0 = __half22float2(sm.u.d.xvp[el0][ip * 3 + m]);
                            float2 v1 = __half22float2(sm.u.d.xvp[el0 + 8][ip * 3 + m]);
                            tv[mt][0][m] += v0.x * w00 + v0.y * w01;
                            tv[mt][1][m] += v1.x * w10 + v1.y * w11;
                        }
                    }
                }
            }
#pragma unroll
            for (int mt = 0; mt < 2; ++mt)
#pragma unroll
                for (int rh = 0; rh < 2; ++rh) {
                    float v = t1[mt][rh];
                    v += __shfl_xor_sync(0xffffffffu, v, 1);
                    v += __shfl_xor_sync(0xffffffffu, v, 2);
                    t1[mt][rh] = v;
#pragma unroll
                    for (int m = 0; m < 3; ++m) {
                        float u2 = tv[mt][rh][m];
                        u2 += __shfl_xor_sync(0xffffffffu, u2, 1);
                        u2 += __shfl_xor_sync(0xffffffffu, u2, 2);
                        tv[mt][rh][m] = u2;
                    }
                }
            float t1j = (j == 0) ? t1[0][0] : (j == 1) ? t1[0][1]
                      : (j == 2) ? t1[1][0] : t1[1][1];
            float tvj[3];
#pragma unroll
            for (int m = 0; m < 3; ++m)
                tvj[m] = (j == 0) ? tv[0][0][m] : (j == 1) ? tv[0][1][m]
                       : (j == 2) ? tv[1][0][m] : tv[1][1][m];
            float* base = arow + 48 + 3 * kk;
            atomicAdd(base + 0, ALPHA * fmaf(t1j, sv_sel0, sss_sel * tvj[0]));
            atomicAdd(base + 1, ALPHA * fmaf(t1j, sv_sel1, sss_sel * tvj[1]));
            atomicAdd(base + 2, ALPHA * fmaf(t1j, sv_sel2, sss_sel * tvj[2]));
        }
    }
}

// ---------------- batchnorm statistics ----------------
__global__ __launch_bounds__(256) void k_stats(const float* __restrict__ bnw) {
    __shared__ float r1[256], r2[256];
    int b = blockIdx.x, t = threadIdx.x;
    float s1 = 0.f, s2 = 0.f;
    if (b < NSC) {
        for (int n = t; n < NNODES; n += 256) {
            float x = g_accum[(size_t)n * 96 + b];
            s1 += x;
            s2 += x * x;
        }
    } else {
        int k = b - NSC;
        for (int n = t; n < NNODES; n += 256) {
            const float* p = &g_accum[(size_t)n * 96 + 48 + 3 * k];
            s2 += p[0] * p[0] + p[1] * p[1] + p[2] * p[2];
        }
    }
    r1[t] = s1;
    r2[t] = s2;
    __syncthreads();
    for (int off = 128; off > 0; off >>= 1) {
        if (t < off) { r1[t] += r1[t + off]; r2[t] += r2[t + off]; }
        __syncthreads();
    }
    if (t == 0) {
        if (b < NSC) {
            float mean = r1[0] / (float)NNODES;
            float var = r2[0] / (float)NNODES - mean * mean;
            g_mean[b] = mean;
            g_rs[b] = rsqrtf(var + BN_EPS) * bnw[b];
        } else {
            int k = b - NSC;
            float vn = r2[0] / (3.0f * (float)NNODES);
            g_rsv[k] = rsqrtf(vn + BN_EPS) * bnw[NSC + k];
        }
    }
}

__global__ void k_final(const float* __restrict__ bnb, float* __restrict__ out) {
    int idx = blockIdx.x * 256 + threadIdx.x;
    if (idx >= NNODES * 96) return;
    int c = idx % 96;
    float x = g_accum[idx];
    float o;
    if (c < NSC) o = (x - g_mean[c]) * g_rs[c] + bnb[c];
    else         o = x * g_rsv[(c - 48) / 3];
    out[idx] = o;
}

// ---------------- launch ----------------
extern "C" void kernel_launch(void* const* d_in, const int* in_sizes, int n_in,
                              void* d_out, int out_size) {
    const float* node_attr = (const float*)d_in[0];
    const int* eidx_raw    = (const int*)d_in[1];
    const float* edge_attr = (const float*)d_in[2];
    const float* edge_sh   = (const float*)d_in[3];
    const float* fc_w1     = (const float*)d_in[4];
    const float* fc_b1     = (const float*)d_in[5];
    const float* fc_w2     = (const float*)d_in[6];
    const float* fc_b2     = (const float*)d_in[7];
    const float* bn_weight = (const float*)d_in[8];
    const float* bn_bias   = (const float*)d_in[9];
    float* out = (float*)d_out;

    cudaFuncSetAttribute(k_tp, cudaFuncAttributeMaxDynamicSharedMemorySize,
                         (int)sizeof(SmemT));

    k_detect_idx<<<1, 256>>>(eidx_raw);
    k_misc<<<(NNODES * 96 + 255) / 256, 256>>>(eidx_raw, node_attr);
    k_prep_frags<<<(NBF_TOTAL + NW1F + NBIAS + 255) / 256, 256>>>(fc_w2, fc_b2, fc_w1);
    k_tp<<<NEDGES / 64, 128, sizeof(SmemT)>>>(node_attr, edge_sh, edge_attr, fc_b1);
    k_stats<<<NSC + NVC, 256>>>(bn_weight);
    k_final<<<(NNODES * 96 + 255) / 256, 256>>>(bn_bias, out);
}

// round 13
// speedup vs baseline: 1.6627x; 1.0737x over previous
#include <cuda_runtime.h>
#include <cuda_fp16.h>
#include <stdint.h>

#define NNODES 4096
#define NEDGES 32768
#define NSC 48
#define NVC 16
#define NEF 128
#define WNUM 4096
#define BN_EPS 1e-5f
#define INV_SQRT3 0.57735026918962576f
#define ALPHA 0.125f

#define NCHUNKS 64
#define KS 8                                  // 8 data ksteps (K=16 each), bias in epilogue
#define BFRAG_PER_CHUNK (KS * 8 * 32)         // uint2 entries = 2048
#define NBF_TOTAL (NCHUNKS * BFRAG_PER_CHUNK) // 131072
#define NW1F 4096                             // 8 ksteps * 16 n8 * 32 lanes
#define NBIAS 2048                            // 64 chunks * 32 half2

// ---------------- static device scratch ----------------
__device__ __align__(16) uint2 g_Bfrag[NBF_TOTAL]; // fp16 W2 fragment images (permuted, pair-interleaved)
__device__ __align__(16) uint2 g_W1frag[NW1F];     // fp16 W1 fragment images
__device__ __align__(16) uint32_t g_b2h[NBIAS];    // permuted fc_b2, half2 pairs
__device__ float g_accum[NNODES * 96];
__device__ float g_mean[NSC];
__device__ float g_rs[NSC];
__device__ float g_rsv[NVC];
__device__ int g_src[NEDGES];
__device__ int g_dst[NEDGES];
__device__ int g_mode;

// ================= helpers =================
__device__ __forceinline__ uint32_t smem_u32(const void* p) {
    uint32_t a;
    asm("{ .reg .u64 t; cvta.to.shared.u64 t, %1; cvt.u32.u64 %0, t; }" : "=r"(a) : "l"(p));
    return a;
}
__device__ __forceinline__ void mma16(float* d, const uint32_t* a, uint32_t b0, uint32_t b1) {
    asm volatile(
        "mma.sync.aligned.m16n8k16.row.col.f32.f16.f16.f32 "
        "{%0,%1,%2,%3}, {%4,%5,%6,%7}, {%8,%9}, {%0,%1,%2,%3};\n"
        : "+f"(d[0]), "+f"(d[1]), "+f"(d[2]), "+f"(d[3])
        : "r"(a[0]), "r"(a[1]), "r"(a[2]), "r"(a[3]), "r"(b0), "r"(b1));
}
__device__ __forceinline__ void cpa16(uint32_t s, const void* g) {
    asm volatile("cp.async.ca.shared.global [%0], [%1], 16;" :: "r"(s), "l"(g));
}
#define CP_COMMIT() asm volatile("cp.async.commit_group;" ::: "memory")
#define CP_WAIT0()  asm volatile("cp.async.wait_group 0;" ::: "memory")

__device__ __forceinline__ float dlrelu(float x) { return (fabsf(x) <= 10.f) ? x : 0.01f * x; }
__device__ __forceinline__ uint32_t pack_relu(float a, float b) {
    __half2 h = __floats2half2_rn(fmaxf(a, 0.f), fmaxf(b, 0.f));
    return *reinterpret_cast<uint32_t*>(&h);
}

// 4-lane reduce-scatter over quad (lanes differ in bits 0..1 = q).
// v[mt][rh]; returns sum over the quad of value (mt = q>>1, rh = q&1).
__device__ __forceinline__ float rs4(float v00, float v01, float v10, float v11, int q) {
    float k0 = (q & 1) ? v01 : v00;
    float s0 = (q & 1) ? v00 : v01;
    float k1 = (q & 1) ? v11 : v10;
    float s1 = (q & 1) ? v10 : v11;
    k0 += __shfl_xor_sync(0xffffffffu, s0, 1);
    k1 += __shfl_xor_sync(0xffffffffu, s1, 1);
    float k = (q >> 1) ? k1 : k0;
    float s = (q >> 1) ? k0 : k1;
    return k + __shfl_xor_sync(0xffffffffu, s, 2);
}

// column permutation: jp (permuted) -> original j of fc_w2
__device__ __forceinline__ int jorig_of(int jp) {
    int chunk = jp >> 6, q = jp & 63;
    if (chunk < 48) {
        return (q < 48) ? q * 48 + chunk : 2304 + (q - 48) * 48 + chunk;
    }
    int k = chunk - 48;
    return (q < 48) ? 3072 + q * 16 + k : 3840 + (q - 48) * 16 + k;
}

// ================= small prep kernels =================
__global__ void k_detect_idx(const int* __restrict__ raw) {
    __shared__ int flag;
    int t = threadIdx.x;
    if (t == 0) flag = 0;
    __syncthreads();
    for (int i = t; i < 2048; i += 256)
        if (raw[2 * i + 1] != 0) flag = 1;
    __syncthreads();
    if (t == 0) g_mode = flag;
}
// idx convert + accumulator init (merged)
__global__ void k_misc(const int* __restrict__ raw, const float* __restrict__ na) {
    int idx = blockIdx.x * 256 + threadIdx.x;
    if (idx < NEDGES) {
        if (g_mode) { g_src[idx] = raw[idx]; g_dst[idx] = raw[NEDGES + idx]; }
        else        { g_src[idx] = raw[2 * idx]; g_dst[idx] = raw[2 * (NEDGES + idx)]; }
    }
    if (idx < NNODES * 96) g_accum[idx] = na[idx];
}
// build fp16 fragment images: W2 (permuted, pair-interleaved for LDS.128), W1, b2 table
__global__ void k_prep_frags(const float* __restrict__ w2,
                             const float* __restrict__ b2,
                             const float* __restrict__ w1) {
    int idx = blockIdx.x * 256 + threadIdx.x;
    if (idx < NBF_TOTAL) {
        int lane = idx & 31;
        int g8 = (idx >> 5) & 7;
        int rest = idx >> 8;        // chunk*8 + s
        int s = rest & 7, chunk = rest >> 3;
        int q = g8 * 8 + (lane >> 2);
        int jo = jorig_of(chunk * 64 + q);
        int k0 = s * 16 + (lane & 3) * 2;
        float f[4];
#pragma unroll
        for (int r = 0; r < 4; ++r) {
            int k = k0 + (r >> 1) * 8 + (r & 1);
            f[r] = w2[(size_t)k * WNUM + jo];
        }
        uint2 out;
        __half2 h0 = __floats2half2_rn(f[0], f[1]);
        __half2 h1 = __floats2half2_rn(f[2], f[3]);
        out.x = *reinterpret_cast<uint32_t*>(&h0);
        out.y = *reinterpret_cast<uint32_t*>(&h1);
        // pair-interleaved layout: uint4 per lane covers fragments g8=2p2, 2p2+1
        int pos = chunk * BFRAG_PER_CHUNK + (s * 4 + (g8 >> 1)) * 64 + lane * 2 + (g8 & 1);
        g_Bfrag[pos] = out;
    } else if (idx < NBF_TOTAL + NW1F) {
        int v = idx - NBF_TOTAL;
        int lane = v & 31;
        int g = (v >> 5) & 15;
        int s = v >> 9;             // 0..7
        int col = g * 8 + (lane >> 2);
        int k0 = s * 16 + (lane & 3) * 2;
        float f[4];
#pragma unroll
        for (int r = 0; r < 4; ++r) {
            int k = k0 + (r >> 1) * 8 + (r & 1);
            f[r] = w1[k * 128 + col];
        }
        uint2 out;
        __half2 h0 = __floats2half2_rn(f[0], f[1]);
        __half2 h1 = __floats2half2_rn(f[2], f[3]);
        out.x = *reinterpret_cast<uint32_t*>(&h0);
        out.y = *reinterpret_cast<uint32_t*>(&h1);
        g_W1frag[v] = out;
    } else if (idx < NBF_TOTAL + NW1F + NBIAS) {
        int v = idx - NBF_TOTAL - NW1F;
        int c = v >> 5, i = v & 31;
        int g8 = i >> 2, q = i & 3;
        int q0 = g8 * 8 + q * 2;
        __half2 h = __floats2half2_rn(b2[jorig_of(c * 64 + q0)],
                                      b2[jorig_of(c * 64 + q0 + 1)]);
        g_b2h[v] = *reinterpret_cast<uint32_t*>(&h);
    }
}

// ================= fused stage-A + fp16 mma GEMM + tensor product + scatter =================
struct SmemT {
    uint2 B[2][BFRAG_PER_CHUNK];   // 32768 B — holds W1frag during prologue
    union {
        __half eah[64 * 144];      // 18432 B (prologue ea image)
        struct {
            __half2 xs2[64][25];   // 6400
            __half2 xvp[64][25];   // 6400
            __half2 dotv2[64][9];  // 2304
            uint32_t bias[NBIAS];  // 8192
        } d;                       // 23296
    } u;
};   // total 56064 B -> 4 CTAs/SM

extern __shared__ __align__(16) char smemraw[];

__global__ __launch_bounds__(128, 4) void k_tp(const float* __restrict__ na,
                                               const float* __restrict__ sh,
                                               const float* __restrict__ ea,
                                               const float* __restrict__ b1) {
    SmemT& sm = *reinterpret_cast<SmemT*>(smemraw);
    int t = threadIdx.x, lane = t & 31, w = t >> 5;
    int h = w & 1;                 // n-half
    int mb = (w >> 1) * 32;        // m-block base (32 edges)
    int ebase = blockIdx.x * 64;
    int r = lane >> 2, q = lane & 3;

    // per-thread fixed output edge (used only at the final atomics)
    int el_sel = mb + (q >> 1) * 16 + (q & 1) * 8 + r;
    float* arow;
    float sss_sel, sv_sel0, sv_sel1, sv_sel2;
    {
        int e = ebase + el_sel;
        arow = g_accum + (size_t)g_dst[e] * 96;
        float4 shv = __ldg(reinterpret_cast<const float4*>(sh) + e);
        sss_sel = shv.x; sv_sel0 = shv.y; sv_sel1 = shv.z; sv_sel2 = shv.w;
    }

    // ---- 1: stream W1 fragment images into the B double-buffer area (32 KB) ----
    {
        uint32_t sB = smem_u32(&sm.B[0][0]);
        const char* g = (const char*)g_W1frag;
#pragma unroll
        for (int i = 0; i < 16; ++i) cpa16(sB + (t + 128 * i) * 16, g + (t + 128 * i) * 16);
        CP_COMMIT();
    }
    // ---- 2: ea tile -> fp16 permuted smem image ----
    __half* eah = sm.u.eah;
    for (int i = t; i < 64 * 64; i += 128) {
        int e = i >> 6, c = (i & 63) * 2;
        float2 v = *reinterpret_cast<const float2*>(ea + (size_t)(ebase + e) * 128 + c);
        int s = c >> 4, ww = c & 15;
        int pos = ((ww & 7) >> 1) * 4 + ((ww >> 3) << 1);
        __half2 hp = __floats2half2_rn(v.x, v.y);
        *reinterpret_cast<__half2*>(eah + e * 144 + s * 16 + pos) = hp;
    }
    CP_WAIT0();
    __syncthreads();

    // ---- 3: prologue MMA — compute H fragments; b1 folded into acc init ----
    uint32_t afr[2][KS][4];
    const uint2* w1f = reinterpret_cast<const uint2*>(&sm.B[0][0]);
    const float2* b1f2 = reinterpret_cast<const float2*>(b1);
#pragma unroll
    for (int mt = 0; mt < 2; ++mt) {
        float accH[16][4];
#pragma unroll
        for (int g = 0; g < 16; ++g) {
            float2 bv = __ldg(&b1f2[g * 4 + q]);
            accH[g][0] = bv.x; accH[g][1] = bv.y;
            accH[g][2] = bv.x; accH[g][3] = bv.y;
        }
        const __half* row0 = eah + (mb + mt * 16 + r) * 144;
        const __half* row8 = row0 + 8 * 144;
#pragma unroll 1
        for (int s = 0; s < KS; ++s) {
            uint2 ae0 = *reinterpret_cast<const uint2*>(row0 + s * 16 + q * 4);
            uint2 ae1 = *reinterpret_cast<const uint2*>(row8 + s * 16 + q * 4);
            uint32_t af[4] = {ae0.x, ae1.x, ae0.y, ae1.y};
#pragma unroll
            for (int g = 0; g < 16; ++g) {
                uint2 bf = w1f[(s * 16 + g) * 32 + lane];
                mma16(accH[g], af, bf.x, bf.y);
            }
        }
#pragma unroll
        for (int sp = 0; sp < KS; ++sp) {
            afr[mt][sp][0] = pack_relu(accH[2 * sp][0], accH[2 * sp][1]);
            afr[mt][sp][1] = pack_relu(accH[2 * sp][2], accH[2 * sp][3]);
            afr[mt][sp][2] = pack_relu(accH[2 * sp + 1][0], accH[2 * sp + 1][1]);
            afr[mt][sp][3] = pack_relu(accH[2 * sp + 1][2], accH[2 * sp + 1][3]);
        }
    }
    __syncthreads();   // all warps done reading W1frag / ea_h

    // ---- 4: start B pipeline (chunk 0 -> buf 0) + bias table ----
    {
        uint32_t sB = smem_u32(&sm.B[0][0]);
        const char* g = (const char*)g_Bfrag;
#pragma unroll
        for (int i = 0; i < 8; ++i) cpa16(sB + (t + 128 * i) * 16, g + (t + 128 * i) * 16);
        uint32_t sBias = smem_u32(&sm.u.d.bias[0]);
        const char* gb = (const char*)g_b2h;
#pragma unroll
        for (int i = 0; i < 4; ++i) cpa16(sBias + (t + 128 * i) * 16, gb + (t + 128 * i) * 16);
        CP_COMMIT();
    }
    // ---- 5: per-edge node data -> fp16 packed tables (overwrites dead ea image) ----
    if (t < 64) {
        int e = ebase + t;
        float4 shv = __ldg(reinterpret_cast<const float4*>(sh) + e);
        __half* xsh = reinterpret_cast<__half*>(&sm.u.d.xs2[t][0]);
        __half* xvh = reinterpret_cast<__half*>(&sm.u.d.xvp[t][0]);
        __half* dth = reinterpret_cast<__half*>(&sm.u.d.dotv2[t][0]);
        const float4* nr = reinterpret_cast<const float4*>(na + (size_t)g_src[e] * 96);
        float dac[16];
#pragma unroll
        for (int i = 0; i < 16; ++i) dac[i] = 0.f;
        float svm[3] = {shv.y, shv.z, shv.w};
#pragma unroll
        for (int qq = 0; qq < 24; ++qq) {
            float4 v = __ldg(nr + qq);
            float vv[4] = {v.x, v.y, v.z, v.w};
#pragma unroll
            for (int jj = 0; jj < 4; ++jj) {
                int c = qq * 4 + jj;
                if (c < 48) {
                    xsh[c] = __float2half(vv[jj]);
                } else {
                    int d = c - 48;
                    int i = d / 3, m = d % 3;
                    dac[i] += vv[jj] * svm[m];
                    xvh[((i >> 1) * 3 + m) * 2 + (i & 1)] = __float2half(vv[jj]);
                }
            }
        }
#pragma unroll
        for (int i = 0; i < 16; ++i)
            dth[i] = __float2half(INV_SQRT3 * dac[i]);
    }

    // ---- 6: main loop ----
#pragma unroll 1
    for (int c = 0; c < NCHUNKS; ++c) {
        int p = c & 1;
        CP_WAIT0();
        __syncthreads();
        if (c + 1 < NCHUNKS) {
            uint32_t sB = smem_u32(&sm.B[1 - p][0]);
            const char* g = (const char*)(g_Bfrag + (size_t)(c + 1) * BFRAG_PER_CHUNK);
#pragma unroll
            for (int i = 0; i < 8; ++i) cpa16(sB + (t + 128 * i) * 16, g + (t + 128 * i) * 16);
        }
        CP_COMMIT();
        // ---- MMA: m32 x n32 per warp, K=128, LDS.128 B loads ----
        float acc[2][4][4];
#pragma unroll
        for (int mt = 0; mt < 2; ++mt)
#pragma unroll
            for (int b = 0; b < 4; ++b)
#pragma unroll
                for (int rr = 0; rr < 4; ++rr) acc[mt][b][rr] = 0.f;
#pragma unroll
        for (int s = 0; s < KS; ++s) {
#pragma unroll
            for (int pp = 0; pp < 2; ++pp) {
                uint4 bf = *reinterpret_cast<const uint4*>(
                    &sm.B[p][(s * 4 + h * 2 + pp) * 64 + lane * 2]);
                mma16(acc[0][2 * pp],     afr[0][s], bf.x, bf.y);
                mma16(acc[1][2 * pp],     afr[1][s], bf.x, bf.y);
                mma16(acc[0][2 * pp + 1], afr[0][s], bf.z, bf.w);
                mma16(acc[1][2 * pp + 1], afr[1][s], bf.z, bf.w);
            }
        }
        // ---- epilogue (bias added here) ----
        float2 bb[4];
#pragma unroll
        for (int b = 0; b < 4; ++b)
            bb[b] = __half22float2(*reinterpret_cast<const __half2*>(
                &sm.u.d.bias[c * 32 + (h * 4 + b) * 4 + q]));
        if (c < 48) {
            float pxs[2][2] = {{0.f, 0.f}, {0.f, 0.f}};
            float pdot[2][2] = {{0.f, 0.f}, {0.f, 0.f}};
#pragma unroll
            for (int mt = 0; mt < 2; ++mt) {
                int el0 = mb + mt * 16 + r;
#pragma unroll
                for (int b = 0; b < 4; ++b) {
                    int g8 = h * 4 + b;
                    float w00 = dlrelu(acc[mt][b][0] + bb[b].x), w01 = dlrelu(acc[mt][b][1] + bb[b].y);
                    float w10 = dlrelu(acc[mt][b][2] + bb[b].x), w11 = dlrelu(acc[mt][b][3] + bb[b].y);
                    if (g8 < 6) {
                        float2 x0 = __half22float2(sm.u.d.xs2[el0][g8 * 4 + q]);
                        float2 x1 = __half22float2(sm.u.d.xs2[el0 + 8][g8 * 4 + q]);
                        pxs[mt][0] += x0.x * w00 + x0.y * w01;
                        pxs[mt][1] += x1.x * w10 + x1.y * w11;
                    } else {
                        float2 d0 = __half22float2(sm.u.d.dotv2[el0][(g8 - 6) * 4 + q]);
                        float2 d1 = __half22float2(sm.u.d.dotv2[el0 + 8][(g8 - 6) * 4 + q]);
                        pdot[mt][0] += d0.x * w00 + d0.y * w01;
                        pdot[mt][1] += d1.x * w10 + d1.y * w11;
                    }
                }
            }
            float xsj = rs4(pxs[0][0], pxs[0][1], pxs[1][0], pxs[1][1], q);
            float dtj = rs4(pdot[0][0], pdot[0][1], pdot[1][0], pdot[1][1], q);
            atomicAdd(arow + c, ALPHA * fmaf(sss_sel, xsj, dtj));
        } else {
            int kk = c - 48;
            float t1[2][2] = {{0.f, 0.f}, {0.f, 0.f}};
            float tv[2][2][3];
#pragma unroll
            for (int mt = 0; mt < 2; ++mt)
#pragma unroll
                for (int rh = 0; rh < 2; ++rh)
#pragma unroll
                    for (int m = 0; m < 3; ++m) tv[mt][rh][m] = 0.f;
#pragma unroll
            for (int mt = 0; mt < 2; ++mt) {
                int el0 = mb + mt * 16 + r;
#pragma unroll
                for (int b = 0; b < 4; ++b) {
                    int g8 = h * 4 + b;
                    float w00 = dlrelu(acc[mt][b][0] + bb[b].x), w01 = dlrelu(acc[mt][b][1] + bb[b].y);
                    float w10 = dlrelu(acc[mt][b][2] + bb[b].x), w11 = dlrelu(acc[mt][b][3] + bb[b].y);
                    if (g8 < 6) {
                        float2 x0 = __half22float2(sm.u.d.xs2[el0][g8 * 4 + q]);
                        float2 x1 = __half22float2(sm.u.d.xs2[el0 + 8][g8 * 4 + q]);
                        t1[mt][0] += x0.x * w00 + x0.y * w01;
                        t1[mt][1] += x1.x * w10 + x1.y * w11;
                    } else {
                        int ip = (g8 - 6) * 4 + q;
#pragma unroll
                        for (int m = 0; m < 3; ++m) {
                            float2 v0 = __half22float2(sm.u.d.xvp[el0][ip * 3 + m]);
                            float2 v1 = __half22float2(sm.u.d.xvp[el0 + 8][ip * 3 + m]);
                            tv[mt][0][m] += v0.x * w00 + v0.y * w01;
                            tv[mt][1][m] += v1.x * w10 + v1.y * w11;
                        }
                    }
                }
            }
            float t1j = rs4(t1[0][0], t1[0][1], t1[1][0], t1[1][1], q);
            float tvj[3];
#pragma unroll
            for (int m = 0; m < 3; ++m)
                tvj[m] = rs4(tv[0][0][m], tv[0][1][m], tv[1][0][m], tv[1][1][m], q);
            float* base = arow + 48 + 3 * kk;
            atomicAdd(base + 0, ALPHA * fmaf(t1j, sv_sel0, sss_sel * tvj[0]));
            atomicAdd(base + 1, ALPHA * fmaf(t1j, sv_sel1, sss_sel * tvj[1]));
            atomicAdd(base + 2, ALPHA * fmaf(t1j, sv_sel2, sss_sel * tvj[2]));
        }
    }
}

// ---------------- batchnorm statistics ----------------
__global__ __launch_bounds__(256) void k_stats(const float* __restrict__ bnw) {
    __shared__ float r1[256], r2[256];
    int b = blockIdx.x, t = threadIdx.x;
    float s1 = 0.f, s2 = 0.f;
    if (b < NSC) {
        for (int n = t; n < NNODES; n += 256) {
            float x = g_accum[(size_t)n * 96 + b];
            s1 += x;
            s2 += x * x;
        }
    } else {
        int k = b - NSC;
        for (int n = t; n < NNODES; n += 256) {
            const float* p = &g_accum[(size_t)n * 96 + 48 + 3 * k];
            s2 += p[0] * p[0] + p[1] * p[1] + p[2] * p[2];
        }
    }
    r1[t] = s1;
    r2[t] = s2;
    __syncthreads();
    for (int off = 128; off > 0; off >>= 1) {
        if (t < off) { r1[t] += r1[t + off]; r2[t] += r2[t + off]; }
        __syncthreads();
    }
    if (t == 0) {
        if (b < NSC) {
            float mean = r1[0] / (float)NNODES;
            float var = r2[0] / (float)NNODES - mean * mean;
            g_mean[b] = mean;
            g_rs[b] = rsqrtf(var + BN_EPS) * bnw[b];
        } else {
            int k = b - NSC;
            float vn = r2[0] / (3.0f * (float)NNODES);
            g_rsv[k] = rsqrtf(vn + BN_EPS) * bnw[NSC + k];
        }
    }
}

__global__ void k_final(const float* __restrict__ bnb, float* __restrict__ out) {
    int idx = blockIdx.x * 256 + threadIdx.x;
    if (idx >= NNODES * 96) return;
    int c = idx % 96;
    float x = g_accum[idx];
    float o;
    if (c < NSC) o = (x - g_mean[c]) * g_rs[c] + bnb[c];
    else         o = x * g_rsv[(c - 48) / 3];
    out[idx] = o;
}

// ---------------- launch ----------------
extern "C" void kernel_launch(void* const* d_in, const int* in_sizes, int n_in,
                              void* d_out, int out_size) {
    const float* node_attr = (const float*)d_in[0];
    const int* eidx_raw    = (const int*)d_in[1];
    const float* edge_attr = (const float*)d_in[2];
    const float* edge_sh   = (const float*)d_in[3];
    const float* fc_w1     = (const float*)d_in[4];
    const float* fc_b1     = (const float*)d_in[5];
    const float* fc_w2     = (const float*)d_in[6];
    const float* fc_b2     = (const float*)d_in[7];
    const float* bn_weight = (const float*)d_in[8];
    const float* bn_bias   = (const float*)d_in[9];
    float* out = (float*)d_out;

    cudaFuncSetAttribute(k_tp, cudaFuncAttributeMaxDynamicSharedMemorySize,
                         (int)sizeof(SmemT));

    k_detect_idx<<<1, 256>>>(eidx_raw);
    k_misc<<<(NNODES * 96 + 255) / 256, 256>>>(eidx_raw, node_attr);
    k_prep_frags<<<(NBF_TOTAL + NW1F + NBIAS + 255) / 256, 256>>>(fc_w2, fc_b2, fc_w1);
    k_tp<<<NEDGES / 64, 128, sizeof(SmemT)>>>(node_attr, edge_sh, edge_attr, fc_b1);
    k_stats<<<NSC + NVC, 256>>>(bn_weight);
    k_final<<<(NNODES * 96 + 255) / 256, 256>>>(bn_bias, out);
}

// round 14
// speedup vs baseline: 1.7435x; 1.0486x over previous
#include <cuda_runtime.h>
#include <cuda_fp16.h>
#include <stdint.h>

#define NNODES 4096
#define NEDGES 32768
#define NSC 48
#define NVC 16
#define NEF 128
#define WNUM 4096
#define BN_EPS 1e-5f
#define INV_SQRT3 0.57735026918962576f
#define ALPHA 0.125f

#define NCHUNKS 64
#define KS 8                                  // 8 data ksteps (K=16 each), bias in epilogue
#define BFRAG_PER_CHUNK (KS * 8 * 32)         // uint2 entries = 2048
#define NBF_TOTAL (NCHUNKS * BFRAG_PER_CHUNK) // 131072
#define NW1F 4096                             // 8 ksteps * 16 n8 * 32 lanes
#define NBIAS 2048                            // 64 chunks * 32 half2

// ---------------- static device scratch ----------------
__device__ __align__(16) uint2 g_Bfrag[NBF_TOTAL]; // fp16 W2 fragment images (permuted, pair-interleaved)
__device__ __align__(16) uint2 g_W1frag[NW1F];     // fp16 W1 fragment images
__device__ __align__(16) uint32_t g_b2h[NBIAS];    // permuted fc_b2, half2 pairs, [c][q][g8]
__device__ float g_accum[NNODES * 96];
__device__ float g_mean[NSC];
__device__ float g_rs[NSC];
__device__ float g_rsv[NVC];
__device__ int g_src[NEDGES];
__device__ int g_dst[NEDGES];

// ================= helpers =================
__device__ __forceinline__ uint32_t smem_u32(const void* p) {
    uint32_t a;
    asm("{ .reg .u64 t; cvta.to.shared.u64 t, %1; cvt.u32.u64 %0, t; }" : "=r"(a) : "l"(p));
    return a;
}
__device__ __forceinline__ void mma16(float* d, const uint32_t* a, uint32_t b0, uint32_t b1) {
    asm volatile(
        "mma.sync.aligned.m16n8k16.row.col.f32.f16.f16.f32 "
        "{%0,%1,%2,%3}, {%4,%5,%6,%7}, {%8,%9}, {%0,%1,%2,%3};\n"
        : "+f"(d[0]), "+f"(d[1]), "+f"(d[2]), "+f"(d[3])
        : "r"(a[0]), "r"(a[1]), "r"(a[2]), "r"(a[3]), "r"(b0), "r"(b1));
}
__device__ __forceinline__ void cpa16(uint32_t s, const void* g) {
    asm volatile("cp.async.ca.shared.global [%0], [%1], 16;" :: "r"(s), "l"(g));
}
#define CP_COMMIT() asm volatile("cp.async.commit_group;" ::: "memory")
#define CP_WAIT0()  asm volatile("cp.async.wait_group 0;" ::: "memory")

__device__ __forceinline__ float dlrelu(float x) { return (fabsf(x) <= 10.f) ? x : 0.01f * x; }
__device__ __forceinline__ uint32_t pack_relu(float a, float b) {
    __half2 h = __floats2half2_rn(fmaxf(a, 0.f), fmaxf(b, 0.f));
    return *reinterpret_cast<uint32_t*>(&h);
}

// 4-lane reduce-scatter over quad (lanes differ in bits 0..1 = q).
__device__ __forceinline__ float rs4(float v00, float v01, float v10, float v11, int q) {
    float k0 = (q & 1) ? v01 : v00;
    float s0 = (q & 1) ? v00 : v01;
    float k1 = (q & 1) ? v11 : v10;
    float s1 = (q & 1) ? v10 : v11;
    k0 += __shfl_xor_sync(0xffffffffu, s0, 1);
    k1 += __shfl_xor_sync(0xffffffffu, s1, 1);
    float k = (q >> 1) ? k1 : k0;
    float s = (q >> 1) ? k0 : k1;
    return k + __shfl_xor_sync(0xffffffffu, s, 2);
}

// column permutation: jp (permuted) -> original j of fc_w2
__device__ __forceinline__ int jorig_of(int jp) {
    int chunk = jp >> 6, q = jp & 63;
    if (chunk < 48) {
        return (q < 48) ? q * 48 + chunk : 2304 + (q - 48) * 48 + chunk;
    }
    int k = chunk - 48;
    return (q < 48) ? 3072 + q * 16 + k : 3840 + (q - 48) * 16 + k;
}

// ================= small prep kernels =================
// dtype detect (per block) + idx convert + accumulator init
__global__ void k_misc(const int* __restrict__ raw, const float* __restrict__ na) {
    int idx = blockIdx.x * 256 + threadIdx.x;
    int local = (idx < NEDGES && raw[2 * idx + 1] != 0) ? 1 : 0;
    int is32 = __syncthreads_or(local);
    if (idx < NEDGES) {
        if (is32) { g_src[idx] = raw[idx]; g_dst[idx] = raw[NEDGES + idx]; }
        else      { g_src[idx] = raw[2 * idx]; g_dst[idx] = raw[2 * (NEDGES + idx)]; }
    }
    if (idx < NNODES * 96) g_accum[idx] = na[idx];
}
// build fp16 fragment images: W2 (permuted, pair-interleaved for LDS.128), W1, b2 table
__global__ void k_prep_frags(const float* __restrict__ w2,
                             const float* __restrict__ b2,
                             const float* __restrict__ w1) {
    int idx = blockIdx.x * 256 + threadIdx.x;
    if (idx < NBF_TOTAL) {
        int lane = idx & 31;
        int g8 = (idx >> 5) & 7;
        int rest = idx >> 8;        // chunk*8 + s
        int s = rest & 7, chunk = rest >> 3;
        int q = g8 * 8 + (lane >> 2);
        int jo = jorig_of(chunk * 64 + q);
        int k0 = s * 16 + (lane & 3) * 2;
        float f[4];
#pragma unroll
        for (int r = 0; r < 4; ++r) {
            int k = k0 + (r >> 1) * 8 + (r & 1);
            f[r] = w2[(size_t)k * WNUM + jo];
        }
        uint2 out;
        __half2 h0 = __floats2half2_rn(f[0], f[1]);
        __half2 h1 = __floats2half2_rn(f[2], f[3]);
        out.x = *reinterpret_cast<uint32_t*>(&h0);
        out.y = *reinterpret_cast<uint32_t*>(&h1);
        // pair-interleaved: uint4 per lane covers fragments g8=2p, 2p+1
        int pos = chunk * BFRAG_PER_CHUNK + (s * 4 + (g8 >> 1)) * 64 + lane * 2 + (g8 & 1);
        g_Bfrag[pos] = out;
    } else if (idx < NBF_TOTAL + NW1F) {
        int v = idx - NBF_TOTAL;
        int lane = v & 31;
        int g = (v >> 5) & 15;
        int s = v >> 9;             // 0..7
        int col = g * 8 + (lane >> 2);
        int k0 = s * 16 + (lane & 3) * 2;
        float f[4];
#pragma unroll
        for (int r = 0; r < 4; ++r) {
            int k = k0 + (r >> 1) * 8 + (r & 1);
            f[r] = w1[k * 128 + col];
        }
        uint2 out;
        __half2 h0 = __floats2half2_rn(f[0], f[1]);
        __half2 h1 = __floats2half2_rn(f[2], f[3]);
        out.x = *reinterpret_cast<uint32_t*>(&h0);
        out.y = *reinterpret_cast<uint32_t*>(&h1);
        g_W1frag[v] = out;
    } else if (idx < NBF_TOTAL + NW1F + NBIAS) {
        int v = idx - NBF_TOTAL - NW1F;
        int c = v >> 5, i = v & 31;
        int q = i >> 3, g8 = i & 7;       // layout [c][q][g8]
        int q0 = g8 * 8 + q * 2;
        __half2 h = __floats2half2_rn(b2[jorig_of(c * 64 + q0)],
                                      b2[jorig_of(c * 64 + q0 + 1)]);
        g_b2h[v] = *reinterpret_cast<uint32_t*>(&h);
    }
}

// ================= fused stage-A + fp16 mma GEMM + tensor product + scatter =================
struct SmemT {
    uint2 B[2][BFRAG_PER_CHUNK];   // 32768 B — holds W1frag during prologue
    union {
        __half eah[64 * 144];      // 18432 B (prologue ea image)
        struct {
            __half2 T1[64 * 36];   // 9216: [el][q][g8] xs pairs (g8<6) / dot pairs (g8>=6), stride 36
            __half2 xvp[64][25];   // 6400
            uint32_t bias[NBIAS];  // 8192: [c][q][g8]
        } d;                       // 23808
    } u;
};   // total 56576 B -> 4 CTAs/SM

extern __shared__ __align__(16) char smemraw[];

__global__ __launch_bounds__(128, 4) void k_tp(const float* __restrict__ na,
                                               const float* __restrict__ sh,
                                               const float* __restrict__ ea,
                                               const float* __restrict__ b1) {
    SmemT& sm = *reinterpret_cast<SmemT*>(smemraw);
    int t = threadIdx.x, lane = t & 31, w = t >> 5;
    int h = w & 1;                 // n-half
    int mb = (w >> 1) * 32;        // m-block base (32 edges)
    int ebase = blockIdx.x * 64;
    int r = lane >> 2, q = lane & 3;

    // per-thread fixed output edge (used only at the final atomics)
    int el_sel = mb + (q >> 1) * 16 + (q & 1) * 8 + r;
    float* arow;
    float sss_sel, sv_sel0, sv_sel1, sv_sel2;
    {
        int e = ebase + el_sel;
        arow = g_accum + (size_t)g_dst[e] * 96;
        float4 shv = __ldg(reinterpret_cast<const float4*>(sh) + e);
        sss_sel = shv.x; sv_sel0 = shv.y; sv_sel1 = shv.z; sv_sel2 = shv.w;
    }

    // ---- 1: stream W1 fragment images into the B double-buffer area (32 KB) ----
    {
        uint32_t sB = smem_u32(&sm.B[0][0]);
        const char* g = (const char*)g_W1frag;
#pragma unroll
        for (int i = 0; i < 16; ++i) cpa16(sB + (t + 128 * i) * 16, g + (t + 128 * i) * 16);
        CP_COMMIT();
    }
    // ---- 2: ea tile -> fp16 permuted smem image ----
    __half* eah = sm.u.eah;
    for (int i = t; i < 64 * 64; i += 128) {
        int e = i >> 6, c = (i & 63) * 2;
        float2 v = *reinterpret_cast<const float2*>(ea + (size_t)(ebase + e) * 128 + c);
        int s = c >> 4, ww = c & 15;
        int pos = ((ww & 7) >> 1) * 4 + ((ww >> 3) << 1);
        __half2 hp = __floats2half2_rn(v.x, v.y);
        *reinterpret_cast<__half2*>(eah + e * 144 + s * 16 + pos) = hp;
    }
    CP_WAIT0();
    __syncthreads();

    // ---- 3: prologue MMA — compute H fragments; b1 folded into acc init ----
    uint32_t afr[2][KS][4];
    const uint2* w1f = reinterpret_cast<const uint2*>(&sm.B[0][0]);
    const float2* b1f2 = reinterpret_cast<const float2*>(b1);
#pragma unroll
    for (int mt = 0; mt < 2; ++mt) {
        float accH[16][4];
#pragma unroll
        for (int g = 0; g < 16; ++g) {
            float2 bv = __ldg(&b1f2[g * 4 + q]);
            accH[g][0] = bv.x; accH[g][1] = bv.y;
            accH[g][2] = bv.x; accH[g][3] = bv.y;
        }
        const __half* row0 = eah + (mb + mt * 16 + r) * 144;
        const __half* row8 = row0 + 8 * 144;
#pragma unroll 1
        for (int s = 0; s < KS; ++s) {
            uint2 ae0 = *reinterpret_cast<const uint2*>(row0 + s * 16 + q * 4);
            uint2 ae1 = *reinterpret_cast<const uint2*>(row8 + s * 16 + q * 4);
            uint32_t af[4] = {ae0.x, ae1.x, ae0.y, ae1.y};
#pragma unroll
            for (int g = 0; g < 16; ++g) {
                uint2 bf = w1f[(s * 16 + g) * 32 + lane];
                mma16(accH[g], af, bf.x, bf.y);
            }
        }
#pragma unroll
        for (int sp = 0; sp < KS; ++sp) {
            afr[mt][sp][0] = pack_relu(accH[2 * sp][0], accH[2 * sp][1]);
            afr[mt][sp][1] = pack_relu(accH[2 * sp][2], accH[2 * sp][3]);
            afr[mt][sp][2] = pack_relu(accH[2 * sp + 1][0], accH[2 * sp + 1][1]);
            afr[mt][sp][3] = pack_relu(accH[2 * sp + 1][2], accH[2 * sp + 1][3]);
        }
    }
    __syncthreads();   // all warps done reading W1frag / ea_h

    // ---- 4: start B pipeline (chunk 0 -> buf 0) + bias table ----
    {
        uint32_t sB = smem_u32(&sm.B[0][0]);
        const char* g = (const char*)g_Bfrag;
#pragma unroll
        for (int i = 0; i < 8; ++i) cpa16(sB + (t + 128 * i) * 16, g + (t + 128 * i) * 16);
        uint32_t sBias = smem_u32(&sm.u.d.bias[0]);
        const char* gb = (const char*)g_b2h;
#pragma unroll
        for (int i = 0; i < 4; ++i) cpa16(sBias + (t + 128 * i) * 16, gb + (t + 128 * i) * 16);
        CP_COMMIT();
    }
    // ---- 5: per-edge node data -> packed tables (overwrites dead ea image) ----
    if (t < 64) {
        int e = ebase + t;
        float4 shv = __ldg(reinterpret_cast<const float4*>(sh) + e);
        __half* t1h = reinterpret_cast<__half*>(&sm.u.d.T1[(size_t)t * 36]);
        __half* xvh = reinterpret_cast<__half*>(&sm.u.d.xvp[t][0]);
        const float4* nr = reinterpret_cast<const float4*>(na + (size_t)g_src[e] * 96);
        float dac[16];
#pragma unroll
        for (int i = 0; i < 16; ++i) dac[i] = 0.f;
        float svm[3] = {shv.y, shv.z, shv.w};
#pragma unroll
        for (int qq = 0; qq < 24; ++qq) {
            float4 v = __ldg(nr + qq);
            float vv[4] = {v.x, v.y, v.z, v.w};
#pragma unroll
            for (int jj = 0; jj < 4; ++jj) {
                int c = qq * 4 + jj;
                if (c < 48) {
                    // T1 xs entry: g8=c>>3, qi=(c&7)>>1, j=c&1
                    int g8 = c >> 3, qi = (c >> 1) & 3, j = c & 1;
                    t1h[(qi * 8 + g8) * 2 + j] = __float2half(vv[jj]);
                } else {
                    int d = c - 48;
                    int i = d / 3, m = d % 3;
                    dac[i] += vv[jj] * svm[m];
                    xvh[((i >> 1) * 3 + m) * 2 + (i & 1)] = __float2half(vv[jj]);
                }
            }
        }
#pragma unroll
        for (int i = 0; i < 16; ++i) {
            // T1 dot entry: i = (g8-6)*8 + qi*2 + j
            int g8 = 6 + (i >> 3), qi = (i >> 1) & 3, j = i & 1;
            t1h[(qi * 8 + g8) * 2 + j] = __float2half(INV_SQRT3 * dac[i]);
        }
    }

    // ---- 6: main loop ----
#pragma unroll 1
    for (int c = 0; c < NCHUNKS; ++c) {
        int p = c & 1;
        CP_WAIT0();
        __syncthreads();
        if (c + 1 < NCHUNKS) {
            uint32_t sB = smem_u32(&sm.B[1 - p][0]);
            const char* g = (const char*)(g_Bfrag + (size_t)(c + 1) * BFRAG_PER_CHUNK);
#pragma unroll
            for (int i = 0; i < 8; ++i) cpa16(sB + (t + 128 * i) * 16, g + (t + 128 * i) * 16);
        }
        CP_COMMIT();
        // ---- MMA: m32 x n32 per warp, K=128, LDS.128 B loads ----
        float acc[2][4][4];
#pragma unroll
        for (int mt = 0; mt < 2; ++mt)
#pragma unroll
            for (int b = 0; b < 4; ++b)
#pragma unroll
                for (int rr = 0; rr < 4; ++rr) acc[mt][b][rr] = 0.f;
#pragma unroll
        for (int s = 0; s < KS; ++s) {
#pragma unroll
            for (int pp = 0; pp < 2; ++pp) {
                uint4 bf = *reinterpret_cast<const uint4*>(
                    &sm.B[p][(s * 4 + h * 2 + pp) * 64 + lane * 2]);
                mma16(acc[0][2 * pp],     afr[0][s], bf.x, bf.y);
                mma16(acc[1][2 * pp],     afr[1][s], bf.x, bf.y);
                mma16(acc[0][2 * pp + 1], afr[0][s], bf.z, bf.w);
                mma16(acc[1][2 * pp + 1], afr[1][s], bf.z, bf.w);
            }
        }
        // ---- epilogue ----
        // bias: one LDS.128 broadcast (layout [c][q][g8], 4 consecutive g8 at h*4)
        uint4 bw = *reinterpret_cast<const uint4*>(&sm.u.d.bias[c * 32 + q * 8 + h * 4]);
        float2 bb[4];
        {
            const __half2* bh = reinterpret_cast<const __half2*>(&bw);
#pragma unroll
            for (int b = 0; b < 4; ++b) bb[b] = __half22float2(bh[b]);
        }
        if (c < 48) {
            float pxs[2][2] = {{0.f, 0.f}, {0.f, 0.f}};
            float pdot[2][2] = {{0.f, 0.f}, {0.f, 0.f}};
#pragma unroll
            for (int mt = 0; mt < 2; ++mt) {
#pragma unroll
                for (int rh = 0; rh < 2; ++rh) {
                    int el = mb + mt * 16 + rh * 8 + r;
                    uint4 cv = *reinterpret_cast<const uint4*>(
                        &sm.u.d.T1[el * 36 + q * 8 + h * 4]);
                    const __half2* ch = reinterpret_cast<const __half2*>(&cv);
#pragma unroll
                    for (int b = 0; b < 4; ++b) {
                        float2 cf = __half22float2(ch[b]);
                        float w0 = dlrelu(acc[mt][b][rh * 2 + 0] + bb[b].x);
                        float w1 = dlrelu(acc[mt][b][rh * 2 + 1] + bb[b].y);
                        if (h * 4 + b < 6) pxs[mt][rh] += cf.x * w0 + cf.y * w1;
                        else               pdot[mt][rh] += cf.x * w0 + cf.y * w1;
                    }
                }
            }
            float xsj = rs4(pxs[0][0], pxs[0][1], pxs[1][0], pxs[1][1], q);
            float dtj = rs4(pdot[0][0], pdot[0][1], pdot[1][0], pdot[1][1], q);
            atomicAdd(arow + c, ALPHA * fmaf(sss_sel, xsj, dtj));
        } else {
            int kk = c - 48;
            float t1[2][2] = {{0.f, 0.f}, {0.f, 0.f}};
            float tv[2][2][3];
#pragma unroll
            for (int mt = 0; mt < 2; ++mt)
#pragma unroll
                for (int rh = 0; rh < 2; ++rh)
#pragma unroll
                    for (int m = 0; m < 3; ++m) tv[mt][rh][m] = 0.f;
#pragma unroll
            for (int mt = 0; mt < 2; ++mt) {
#pragma unroll
                for (int rh = 0; rh < 2; ++rh) {
                    int el = mb + mt * 16 + rh * 8 + r;
                    uint4 cv = *reinterpret_cast<const uint4*>(
                        &sm.u.d.T1[el * 36 + q * 8 + h * 4]);
                    const __half2* ch = reinterpret_cast<const __half2*>(&cv);
#pragma unroll
                    for (int b = 0; b < 4; ++b) {
                        int g8 = h * 4 + b;
                        float w0 = dlrelu(acc[mt][b][rh * 2 + 0] + bb[b].x);
                        float w1 = dlrelu(acc[mt][b][rh * 2 + 1] + bb[b].y);
                        if (g8 < 6) {
                            float2 cf = __half22float2(ch[b]);
                            t1[mt][rh] += cf.x * w0 + cf.y * w1;
                        } else {
                            int ip = (g8 - 6) * 4 + q;
#pragma unroll
                            for (int m = 0; m < 3; ++m) {
                                float2 v0 = __half22float2(sm.u.d.xvp[el][ip * 3 + m]);
                                tv[mt][rh][m] += v0.x * w0 + v0.y * w1;
                            }
                        }
                    }
                }
            }
            float t1j = rs4(t1[0][0], t1[0][1], t1[1][0], t1[1][1], q);
            float tvj[3];
#pragma unroll
            for (int m = 0; m < 3; ++m)
                tvj[m] = rs4(tv[0][0][m], tv[0][1][m], tv[1][0][m], tv[1][1][m], q);
            float* base = arow + 48 + 3 * kk;
            atomicAdd(base + 0, ALPHA * fmaf(t1j, sv_sel0, sss_sel * tvj[0]));
            atomicAdd(base + 1, ALPHA * fmaf(t1j, sv_sel1, sss_sel * tvj[1]));
            atomicAdd(base + 2, ALPHA * fmaf(t1j, sv_sel2, sss_sel * tvj[2]));
        }
    }
}

// ---------------- batchnorm statistics ----------------
__global__ __launch_bounds__(256) void k_stats(const float* __restrict__ bnw) {
    __shared__ float r1[256], r2[256];
    int b = blockIdx.x, t = threadIdx.x;
    float s1 = 0.f, s2 = 0.f;
    if (b < NSC) {
        for (int n = t; n < NNODES; n += 256) {
            float x = g_accum[(size_t)n * 96 + b];
            s1 += x;
            s2 += x * x;
        }
    } else {
        int k = b - NSC;
        for (int n = t; n < NNODES; n += 256) {
            const float* p = &g_accum[(size_t)n * 96 + 48 + 3 * k];
            s2 += p[0] * p[0] + p[1] * p[1] + p[2] * p[2];
        }
    }
    r1[t] = s1;
    r2[t] = s2;
    __syncthreads();
    for (int off = 128; off > 0; off >>= 1) {
        if (t < off) { r1[t] += r1[t + off]; r2[t] += r2[t + off]; }
        __syncthreads();
    }
    if (t == 0) {
        if (b < NSC) {
            float mean = r1[0] / (float)NNODES;
            float var = r2[0] / (float)NNODES - mean * mean;
            g_mean[b] = mean;
            g_rs[b] = rsqrtf(var + BN_EPS) * bnw[b];
        } else {
            int k = b - NSC;
            float vn = r2[0] / (3.0f * (float)NNODES);
            g_rsv[k] = rsqrtf(vn + BN_EPS) * bnw[NSC + k];
        }
    }
}

__global__ void k_final(const float* __restrict__ bnb, float* __restrict__ out) {
    int idx = blockIdx.x * 256 + threadIdx.x;
    if (idx >= NNODES * 96) return;
    int c = idx % 96;
    float x = g_accum[idx];
    float o;
    if (c < NSC) o = (x - g_mean[c]) * g_rs[c] + bnb[c];
    else         o = x * g_rsv[(c - 48) / 3];
    out[idx] = o;
}

// ---------------- launch ----------------
extern "C" void kernel_launch(void* const* d_in, const int* in_sizes, int n_in,
                              void* d_out, int out_size) {
    const float* node_attr = (const float*)d_in[0];
    const int* eidx_raw    = (const int*)d_in[1];
    const float* edge_attr = (const float*)d_in[2];
    const float* edge_sh   = (const float*)d_in[3];
    const float* fc_w1     = (const float*)d_in[4];
    const float* fc_b1     = (const float*)d_in[5];
    const float* fc_w2     = (const float*)d_in[6];
    const float* fc_b2     = (const float*)d_in[7];
    const float* bn_weight = (const float*)d_in[8];
    const float* bn_bias   = (const float*)d_in[9];
    float* out = (float*)d_out;

    cudaFuncSetAttribute(k_tp, cudaFuncAttributeMaxDynamicSharedMemorySize,
                         (int)sizeof(SmemT));

    k_misc<<<(NNODES * 96 + 255) / 256, 256>>>(eidx_raw, node_attr);
    k_prep_frags<<<(NBF_TOTAL + NW1F + NBIAS + 255) / 256, 256>>>(fc_w2, fc_b2, fc_w1);
    k_tp<<<NEDGES / 64, 128, sizeof(SmemT)>>>(node_attr, edge_sh, edge_attr, fc_b1);
    k_stats<<<NSC + NVC, 256>>>(bn_weight);
    k_final<<<(NNODES * 96 + 255) / 256, 256>>>(bn_bias, out);
}

// round 15
// speedup vs baseline: 1.8050x; 1.0353x over previous
#include <cuda_runtime.h>
#include <cuda_fp16.h>
#include <stdint.h>

#define NNODES 4096
#define NEDGES 32768
#define NSC 48
#define NVC 16
#define NEF 128
#define WNUM 4096
#define BN_EPS 1e-5f
#define INV_SQRT3 0.57735026918962576f
#define ALPHA 0.125f

#define NCHUNKS 64
#define KS 8                                  // 8 data ksteps (K=16 each), bias in epilogue
#define BFRAG_PER_CHUNK (KS * 8 * 32)         // uint2 entries = 2048
#define NBF_TOTAL (NCHUNKS * BFRAG_PER_CHUNK) // 131072
#define NW1F 4096                             // 8 ksteps * 16 n8 * 32 lanes
#define NBIAS 2048                            // 64 chunks * 32 half2

// ---------------- static device scratch ----------------
__device__ __align__(16) uint2 g_Bfrag[NBF_TOTAL]; // fp16 W2 fragment images (permuted, pair-interleaved)
__device__ __align__(16) uint2 g_W1frag[NW1F];     // fp16 W1 fragment images
__device__ __align__(16) uint32_t g_b2h[NBIAS];    // permuted fc_b2, half2 pairs, [c][q][g8]
__device__ float g_accum[NNODES * 96];
__device__ float g_ps1[NSC];                       // partial sums (scalar channels)
__device__ float g_ps2[NSC + NVC];                 // partial sumsq (48 scalar + 16 vector bins)
__device__ float g_mean[NSC];
__device__ float g_rs[NSC];
__device__ float g_rsv[NVC];
__device__ int g_src[NEDGES];
__device__ int g_dst[NEDGES];

// ================= helpers =================
__device__ __forceinline__ uint32_t smem_u32(const void* p) {
    uint32_t a;
    asm("{ .reg .u64 t; cvta.to.shared.u64 t, %1; cvt.u32.u64 %0, t; }" : "=r"(a) : "l"(p));
    return a;
}
__device__ __forceinline__ void mma16(float* d, const uint32_t* a, uint32_t b0, uint32_t b1) {
    asm volatile(
        "mma.sync.aligned.m16n8k16.row.col.f32.f16.f16.f32 "
        "{%0,%1,%2,%3}, {%4,%5,%6,%7}, {%8,%9}, {%0,%1,%2,%3};\n"
        : "+f"(d[0]), "+f"(d[1]), "+f"(d[2]), "+f"(d[3])
        : "r"(a[0]), "r"(a[1]), "r"(a[2]), "r"(a[3]), "r"(b0), "r"(b1));
}
__device__ __forceinline__ void cpa16(uint32_t s, const void* g) {
    asm volatile("cp.async.ca.shared.global [%0], [%1], 16;" :: "r"(s), "l"(g));
}
#define CP_COMMIT() asm volatile("cp.async.commit_group;" ::: "memory")
#define CP_WAIT0()  asm volatile("cp.async.wait_group 0;" ::: "memory")

__device__ __forceinline__ float dlrelu(float x) { return (fabsf(x) <= 10.f) ? x : 0.01f * x; }
__device__ __forceinline__ uint32_t pack_relu(float a, float b) {
    __half2 h = __floats2half2_rn(fmaxf(a, 0.f), fmaxf(b, 0.f));
    return *reinterpret_cast<uint32_t*>(&h);
}

// 4-lane reduce-scatter over quad (lanes differ in bits 0..1 = q).
__device__ __forceinline__ float rs4(float v00, float v01, float v10, float v11, int q) {
    float k0 = (q & 1) ? v01 : v00;
    float s0 = (q & 1) ? v00 : v01;
    float k1 = (q & 1) ? v11 : v10;
    float s1 = (q & 1) ? v10 : v11;
    k0 += __shfl_xor_sync(0xffffffffu, s0, 1);
    k1 += __shfl_xor_sync(0xffffffffu, s1, 1);
    float k = (q >> 1) ? k1 : k0;
    float s = (q >> 1) ? k0 : k1;
    return k + __shfl_xor_sync(0xffffffffu, s, 2);
}

// column permutation: jp (permuted) -> original j of fc_w2
__device__ __forceinline__ int jorig_of(int jp) {
    int chunk = jp >> 6, q = jp & 63;
    if (chunk < 48) {
        return (q < 48) ? q * 48 + chunk : 2304 + (q - 48) * 48 + chunk;
    }
    int k = chunk - 48;
    return (q < 48) ? 3072 + q * 16 + k : 3840 + (q - 48) * 16 + k;
}

// ================= small prep kernels =================
// dtype detect (per block) + idx convert + accumulator init + stats-bin zero
__global__ void k_misc(const int* __restrict__ raw, const float* __restrict__ na) {
    int idx = blockIdx.x * 256 + threadIdx.x;
    int local = (idx < NEDGES && raw[2 * idx + 1] != 0) ? 1 : 0;
    int is32 = __syncthreads_or(local);
    if (idx < NEDGES) {
        if (is32) { g_src[idx] = raw[idx]; g_dst[idx] = raw[NEDGES + idx]; }
        else      { g_src[idx] = raw[2 * idx]; g_dst[idx] = raw[2 * (NEDGES + idx)]; }
    }
    if (idx < NNODES * 96) g_accum[idx] = na[idx];
    if (idx < NSC) g_ps1[idx] = 0.f;
    if (idx < NSC + NVC) g_ps2[idx] = 0.f;
}
// build fp16 fragment images: W2 (permuted, pair-interleaved for LDS.128), W1, b2 table
__global__ void k_prep_frags(const float* __restrict__ w2,
                             const float* __restrict__ b2,
                             const float* __restrict__ w1) {
    int idx = blockIdx.x * 256 + threadIdx.x;
    if (idx < NBF_TOTAL) {
        int lane = idx & 31;
        int g8 = (idx >> 5) & 7;
        int rest = idx >> 8;        // chunk*8 + s
        int s = rest & 7, chunk = rest >> 3;
        int q = g8 * 8 + (lane >> 2);
        int jo = jorig_of(chunk * 64 + q);
        int k0 = s * 16 + (lane & 3) * 2;
        float f[4];
#pragma unroll
        for (int r = 0; r < 4; ++r) {
            int k = k0 + (r >> 1) * 8 + (r & 1);
            f[r] = w2[(size_t)k * WNUM + jo];
        }
        uint2 out;
        __half2 h0 = __floats2half2_rn(f[0], f[1]);
        __half2 h1 = __floats2half2_rn(f[2], f[3]);
        out.x = *reinterpret_cast<uint32_t*>(&h0);
        out.y = *reinterpret_cast<uint32_t*>(&h1);
        // pair-interleaved: uint4 per lane covers fragments g8=2p, 2p+1
        int pos = chunk * BFRAG_PER_CHUNK + (s * 4 + (g8 >> 1)) * 64 + lane * 2 + (g8 & 1);
        g_Bfrag[pos] = out;
    } else if (idx < NBF_TOTAL + NW1F) {
        int v = idx - NBF_TOTAL;
        int lane = v & 31;
        int g = (v >> 5) & 15;
        int s = v >> 9;             // 0..7
        int col = g * 8 + (lane >> 2);
        int k0 = s * 16 + (lane & 3) * 2;
        float f[4];
#pragma unroll
        for (int r = 0; r < 4; ++r) {
            int k = k0 + (r >> 1) * 8 + (r & 1);
            f[r] = w1[k * 128 + col];
        }
        uint2 out;
        __half2 h0 = __floats2half2_rn(f[0], f[1]);
        __half2 h1 = __floats2half2_rn(f[2], f[3]);
        out.x = *reinterpret_cast<uint32_t*>(&h0);
        out.y = *reinterpret_cast<uint32_t*>(&h1);
        g_W1frag[v] = out;
    } else if (idx < NBF_TOTAL + NW1F + NBIAS) {
        int v = idx - NBF_TOTAL - NW1F;
        int c = v >> 5, i = v & 31;
        int q = i >> 3, g8 = i & 7;       // layout [c][q][g8]
        int q0 = g8 * 8 + q * 2;
        __half2 h = __floats2half2_rn(b2[jorig_of(c * 64 + q0)],
                                      b2[jorig_of(c * 64 + q0 + 1)]);
        g_b2h[v] = *reinterpret_cast<uint32_t*>(&h);
    }
}

// ================= fused stage-A + fp16 mma GEMM + tensor product + scatter =================
struct SmemT {
    uint2 B[2][BFRAG_PER_CHUNK];   // 32768 B — holds W1frag during prologue
    union {
        __half eah[64 * 144];      // 18432 B (prologue ea image)
        struct {
            __half2 T1[64 * 36];   // 9216: [el][q][g8] xs pairs (g8<6) / dot pairs (g8>=6), stride 36
            __half2 xvp[64][25];   // 6400
            uint32_t bias[NBIAS];  // 8192: [c][q][g8]
        } d;                       // 23808
    } u;
};   // total 56576 B -> 4 CTAs/SM

extern __shared__ __align__(16) char smemraw[];

__global__ __launch_bounds__(128, 4) void k_tp(const float* __restrict__ na,
                                               const float* __restrict__ sh,
                                               const float* __restrict__ ea,
                                               const float* __restrict__ b1) {
    SmemT& sm = *reinterpret_cast<SmemT*>(smemraw);
    int t = threadIdx.x, lane = t & 31, w = t >> 5;
    int h = w & 1;                 // n-half
    int mb = (w >> 1) * 32;        // m-block base (32 edges)
    int ebase = blockIdx.x * 64;
    int r = lane >> 2, q = lane & 3;

    // per-thread fixed output edge (used only at the final atomics)
    int el_sel = mb + (q >> 1) * 16 + (q & 1) * 8 + r;
    float* arow;
    float sss_sel, sv_sel0, sv_sel1, sv_sel2;
    {
        int e = ebase + el_sel;
        arow = g_accum + (size_t)g_dst[e] * 96;
        float4 shv = __ldg(reinterpret_cast<const float4*>(sh) + e);
        sss_sel = shv.x; sv_sel0 = shv.y; sv_sel1 = shv.z; sv_sel2 = shv.w;
    }

    // ---- 1: stream W1 fragment images into the B double-buffer area (32 KB) ----
    {
        uint32_t sB = smem_u32(&sm.B[0][0]);
        const char* g = (const char*)g_W1frag;
#pragma unroll
        for (int i = 0; i < 16; ++i) cpa16(sB + (t + 128 * i) * 16, g + (t + 128 * i) * 16);
        CP_COMMIT();
    }
    // ---- 2: ea tile -> fp16 permuted smem image ----
    __half* eah = sm.u.eah;
    for (int i = t; i < 64 * 64; i += 128) {
        int e = i >> 6, c = (i & 63) * 2;
        float2 v = *reinterpret_cast<const float2*>(ea + (size_t)(ebase + e) * 128 + c);
        int s = c >> 4, ww = c & 15;
        int pos = ((ww & 7) >> 1) * 4 + ((ww >> 3) << 1);
        __half2 hp = __floats2half2_rn(v.x, v.y);
        *reinterpret_cast<__half2*>(eah + e * 144 + s * 16 + pos) = hp;
    }
    CP_WAIT0();
    __syncthreads();

    // ---- 3: prologue MMA — compute H fragments; b1 folded into acc init ----
    uint32_t afr[2][KS][4];
    const uint2* w1f = reinterpret_cast<const uint2*>(&sm.B[0][0]);
    const float2* b1f2 = reinterpret_cast<const float2*>(b1);
#pragma unroll
    for (int mt = 0; mt < 2; ++mt) {
        float accH[16][4];
#pragma unroll
        for (int g = 0; g < 16; ++g) {
            float2 bv = __ldg(&b1f2[g * 4 + q]);
            accH[g][0] = bv.x; accH[g][1] = bv.y;
            accH[g][2] = bv.x; accH[g][3] = bv.y;
        }
        const __half* row0 = eah + (mb + mt * 16 + r) * 144;
        const __half* row8 = row0 + 8 * 144;
#pragma unroll 1
        for (int s = 0; s < KS; ++s) {
            uint2 ae0 = *reinterpret_cast<const uint2*>(row0 + s * 16 + q * 4);
            uint2 ae1 = *reinterpret_cast<const uint2*>(row8 + s * 16 + q * 4);
            uint32_t af[4] = {ae0.x, ae1.x, ae0.y, ae1.y};
#pragma unroll
            for (int g = 0; g < 16; ++g) {
                uint2 bf = w1f[(s * 16 + g) * 32 + lane];
                mma16(accH[g], af, bf.x, bf.y);
            }
        }
#pragma unroll
        for (int sp = 0; sp < KS; ++sp) {
            afr[mt][sp][0] = pack_relu(accH[2 * sp][0], accH[2 * sp][1]);
            afr[mt][sp][1] = pack_relu(accH[2 * sp][2], accH[2 * sp][3]);
            afr[mt][sp][2] = pack_relu(accH[2 * sp + 1][0], accH[2 * sp + 1][1]);
            afr[mt][sp][3] = pack_relu(accH[2 * sp + 1][2], accH[2 * sp + 1][3]);
        }
    }
    __syncthreads();   // all warps done reading W1frag / ea_h

    // ---- 4: start B pipeline (chunk 0 -> buf 0) + bias table ----
    {
        uint32_t sB = smem_u32(&sm.B[0][0]);
        const char* g = (const char*)g_Bfrag;
#pragma unroll
        for (int i = 0; i < 8; ++i) cpa16(sB + (t + 128 * i) * 16, g + (t + 128 * i) * 16);
        uint32_t sBias = smem_u32(&sm.u.d.bias[0]);
        const char* gb = (const char*)g_b2h;
#pragma unroll
        for (int i = 0; i < 4; ++i) cpa16(sBias + (t + 128 * i) * 16, gb + (t + 128 * i) * 16);
        CP_COMMIT();
    }
    // ---- 5: per-edge node data -> packed tables (overwrites dead ea image) ----
    if (t < 64) {
        int e = ebase + t;
        float4 shv = __ldg(reinterpret_cast<const float4*>(sh) + e);
        __half* t1h = reinterpret_cast<__half*>(&sm.u.d.T1[(size_t)t * 36]);
        __half* xvh = reinterpret_cast<__half*>(&sm.u.d.xvp[t][0]);
        const float4* nr = reinterpret_cast<const float4*>(na + (size_t)g_src[e] * 96);
        float dac[16];
#pragma unroll
        for (int i = 0; i < 16; ++i) dac[i] = 0.f;
        float svm[3] = {shv.y, shv.z, shv.w};
#pragma unroll
        for (int qq = 0; qq < 24; ++qq) {
            float4 v = __ldg(nr + qq);
            float vv[4] = {v.x, v.y, v.z, v.w};
#pragma unroll
            for (int jj = 0; jj < 4; ++jj) {
                int c = qq * 4 + jj;
                if (c < 48) {
                    int g8 = c >> 3, qi = (c >> 1) & 3, j = c & 1;
                    t1h[(qi * 8 + g8) * 2 + j] = __float2half(vv[jj]);
                } else {
                    int d = c - 48;
                    int i = d / 3, m = d % 3;
                    dac[i] += vv[jj] * svm[m];
                    xvh[((i >> 1) * 3 + m) * 2 + (i & 1)] = __float2half(vv[jj]);
                }
            }
        }
#pragma unroll
        for (int i = 0; i < 16; ++i) {
            int g8 = 6 + (i >> 3), qi = (i >> 1) & 3, j = i & 1;
            t1h[(qi * 8 + g8) * 2 + j] = __float2half(INV_SQRT3 * dac[i]);
        }
    }

    // ---- 6: main loop ----
#pragma unroll 1
    for (int c = 0; c < NCHUNKS; ++c) {
        int p = c & 1;
        CP_WAIT0();
        __syncthreads();
        if (c + 1 < NCHUNKS) {
            uint32_t sB = smem_u32(&sm.B[1 - p][0]);
            const char* g = (const char*)(g_Bfrag + (size_t)(c + 1) * BFRAG_PER_CHUNK);
#pragma unroll
            for (int i = 0; i < 8; ++i) cpa16(sB + (t + 128 * i) * 16, g + (t + 128 * i) * 16);
        }
        CP_COMMIT();
        // ---- MMA: m32 x n32 per warp, K=128, LDS.128 B loads ----
        float acc[2][4][4];
#pragma unroll
        for (int mt = 0; mt < 2; ++mt)
#pragma unroll
            for (int b = 0; b < 4; ++b)
#pragma unroll
                for (int rr = 0; rr < 4; ++rr) acc[mt][b][rr] = 0.f;
#pragma unroll
        for (int s = 0; s < KS; ++s) {
#pragma unroll
            for (int pp = 0; pp < 2; ++pp) {
                uint4 bf = *reinterpret_cast<const uint4*>(
                    &sm.B[p][(s * 4 + h * 2 + pp) * 64 + lane * 2]);
                mma16(acc[0][2 * pp],     afr[0][s], bf.x, bf.y);
                mma16(acc[1][2 * pp],     afr[1][s], bf.x, bf.y);
                mma16(acc[0][2 * pp + 1], afr[0][s], bf.z, bf.w);
                mma16(acc[1][2 * pp + 1], afr[1][s], bf.z, bf.w);
            }
        }
        // ---- epilogue ----
        uint4 bw = *reinterpret_cast<const uint4*>(&sm.u.d.bias[c * 32 + q * 8 + h * 4]);
        float2 bb[4];
        {
            const __half2* bh = reinterpret_cast<const __half2*>(&bw);
#pragma unroll
            for (int b = 0; b < 4; ++b) bb[b] = __half22float2(bh[b]);
        }
        if (c < 48) {
            float pxs[2][2] = {{0.f, 0.f}, {0.f, 0.f}};
            float pdot[2][2] = {{0.f, 0.f}, {0.f, 0.f}};
#pragma unroll
            for (int mt = 0; mt < 2; ++mt) {
#pragma unroll
                for (int rh = 0; rh < 2; ++rh) {
                    int el = mb + mt * 16 + rh * 8 + r;
                    uint4 cv = *reinterpret_cast<const uint4*>(
                        &sm.u.d.T1[el * 36 + q * 8 + h * 4]);
                    const __half2* ch = reinterpret_cast<const __half2*>(&cv);
#pragma unroll
                    for (int b = 0; b < 4; ++b) {
                        float2 cf = __half22float2(ch[b]);
                        float w0 = dlrelu(acc[mt][b][rh * 2 + 0] + bb[b].x);
                        float w1 = dlrelu(acc[mt][b][rh * 2 + 1] + bb[b].y);
                        if (h * 4 + b < 6) pxs[mt][rh] += cf.x * w0 + cf.y * w1;
                        else               pdot[mt][rh] += cf.x * w0 + cf.y * w1;
                    }
                }
            }
            float xsj = rs4(pxs[0][0], pxs[0][1], pxs[1][0], pxs[1][1], q);
            float dtj = rs4(pdot[0][0], pdot[0][1], pdot[1][0], pdot[1][1], q);
            atomicAdd(arow + c, ALPHA * fmaf(sss_sel, xsj, dtj));
        } else {
            int kk = c - 48;
            float t1[2][2] = {{0.f, 0.f}, {0.f, 0.f}};
            float tv[2][2][3];
#pragma unroll
            for (int mt = 0; mt < 2; ++mt)
#pragma unroll
                for (int rh = 0; rh < 2; ++rh)
#pragma unroll
                    for (int m = 0; m < 3; ++m) tv[mt][rh][m] = 0.f;
#pragma unroll
            for (int mt = 0; mt < 2; ++mt) {
#pragma unroll
                for (int rh = 0; rh < 2; ++rh) {
                    int el = mb + mt * 16 + rh * 8 + r;
                    uint4 cv = *reinterpret_cast<const uint4*>(
                        &sm.u.d.T1[el * 36 + q * 8 + h * 4]);
                    const __half2* ch = reinterpret_cast<const __half2*>(&cv);
#pragma unroll
                    for (int b = 0; b < 4; ++b) {
                        int g8 = h * 4 + b;
                        float w0 = dlrelu(acc[mt][b][rh * 2 + 0] + bb[b].x);
                        float w1 = dlrelu(acc[mt][b][rh * 2 + 1] + bb[b].y);
                        if (g8 < 6) {
                            float2 cf = __half22float2(ch[b]);
                            t1[mt][rh] += cf.x * w0 + cf.y * w1;
                        } else {
                            int ip = (g8 - 6) * 4 + q;
#pragma unroll
                            for (int m = 0; m < 3; ++m) {
                                float2 v0 = __half22float2(sm.u.d.xvp[el][ip * 3 + m]);
                                tv[mt][rh][m] += v0.x * w0 + v0.y * w1;
                            }
                        }
                    }
                }
            }
            float t1j = rs4(t1[0][0], t1[0][1], t1[1][0], t1[1][1], q);
            float tvj[3];
#pragma unroll
            for (int m = 0; m < 3; ++m)
                tvj[m] = rs4(tv[0][0][m], tv[0][1][m], tv[1][0][m], tv[1][1][m], q);
            float* base = arow + 48 + 3 * kk;
            atomicAdd(base + 0, ALPHA * fmaf(t1j, sv_sel0, sss_sel * tvj[0]));
            atomicAdd(base + 1, ALPHA * fmaf(t1j, sv_sel1, sss_sel * tvj[1]));
            atomicAdd(base + 2, ALPHA * fmaf(t1j, sv_sel2, sss_sel * tvj[2]));
        }
    }
}

// ---------------- batchnorm statistics: coalesced partial reduction ----------------
__global__ __launch_bounds__(192) void k_stats_part() {
    __shared__ float sh1[96], sh2[96];
    int t = threadIdx.x;
    int col = t % 96, ro = t / 96;      // ro in {0,1}
    float s1 = 0.f, s2 = 0.f;
    const float* p = g_accum + (size_t)(blockIdx.x * 32 + ro) * 96 + col;
#pragma unroll 4
    for (int i = 0; i < 16; ++i) {
        float x = p[(size_t)i * 192];   // advance 2 node-rows
        s1 += x;
        s2 += x * x;
    }
    if (ro == 1) { sh1[col] = s1; sh2[col] = s2; }
    __syncthreads();
    if (ro == 0) {
        s1 += sh1[col];
        s2 += sh2[col];
        if (col < NSC) {
            atomicAdd(&g_ps1[col], s1);
            atomicAdd(&g_ps2[col], s2);
        } else {
            int k = (col - NSC) / 3;
            atomicAdd(&g_ps2[NSC + k], s2);
        }
    }
}

__global__ void k_stats_fin(const float* __restrict__ bnw) {
    int t = threadIdx.x;
    if (t < NSC) {
        float mean = g_ps1[t] / (float)NNODES;
        float var = g_ps2[t] / (float)NNODES - mean * mean;
        g_mean[t] = mean;
        g_rs[t] = rsqrtf(var + BN_EPS) * bnw[t];
    } else if (t < NSC + NVC) {
        int k = t - NSC;
        float vn = g_ps2[NSC + k] / (3.0f * (float)NNODES);
        g_rsv[k] = rsqrtf(vn + BN_EPS) * bnw[NSC + k];
    }
}

__global__ void k_final(const float* __restrict__ bnb, float* __restrict__ out) {
    int idx = blockIdx.x * 256 + threadIdx.x;
    if (idx >= NNODES * 96) return;
    int c = idx % 96;
    float x = g_accum[idx];
    float o;
    if (c < NSC) o = (x - g_mean[c]) * g_rs[c] + bnb[c];
    else         o = x * g_rsv[(c - 48) / 3];
    out[idx] = o;
}

// ---------------- launch ----------------
extern "C" void kernel_launch(void* const* d_in, const int* in_sizes, int n_in,
                              void* d_out, int out_size) {
    const float* node_attr = (const float*)d_in[0];
    const int* eidx_raw    = (const int*)d_in[1];
    const float* edge_attr = (const float*)d_in[2];
    const float* edge_sh   = (const float*)d_in[3];
    const float* fc_w1     = (const float*)d_in[4];
    const float* fc_b1     = (const float*)d_in[5];
    const float* fc_w2     = (const float*)d_in[6];
    const float* fc_b2     = (const float*)d_in[7];
    const float* bn_weight = (const float*)d_in[8];
    const float* bn_bias   = (const float*)d_in[9];
    float* out = (float*)d_out;

    cudaFuncSetAttribute(k_tp, cudaFuncAttributeMaxDynamicSharedMemorySize,
                         (int)sizeof(SmemT));

    k_misc<<<(NNODES * 96 + 255) / 256, 256>>>(eidx_raw, node_attr);
    k_prep_frags<<<(NBF_TOTAL + NW1F + NBIAS + 255) / 256, 256>>>(fc_w2, fc_b2, fc_w1);
    k_tp<<<NEDGES / 64, 128, sizeof(SmemT)>>>(node_attr, edge_sh, edge_attr, fc_b1);
    k_stats_part<<<NNODES / 32, 192>>>();
    k_stats_fin<<<1, 64>>>(bn_weight);
    k_final<<<(NNODES * 96 + 255) / 256, 256>>>(bn_bias, out);
}

// round 17
// speedup vs baseline: 2.0077x; 1.1123x over previous
#include <cuda_runtime.h>
#include <cuda_fp16.h>
#include <stdint.h>

#define NNODES 4096
#define NEDGES 32768
#define NSC 48
#define NVC 16
#define NEF 128
#define WNUM 4096
#define BN_EPS 1e-5f
#define INV_SQRT3 0.57735026918962576f
#define ALPHA 0.125f

#define NCHUNKS 64
#define KS 8                                  // 8 data ksteps (K=16 each), bias in epilogue
#define BFRAG_PER_CHUNK (KS * 8 * 32)         // uint2 entries = 2048
#define NBF_TOTAL (NCHUNKS * BFRAG_PER_CHUNK) // 131072
#define NW1F 4096                             // 8 ksteps * 16 n8 * 32 lanes
#define NBIAS 2048                            // 64 chunks * 32 half2
#define EPT 128                               // edges per CTA

// ---------------- static device scratch ----------------
__device__ __align__(16) uint2 g_Bfrag[NBF_TOTAL]; // fp16 W2 fragment images (permuted, pair-interleaved)
__device__ __align__(16) uint2 g_W1frag[NW1F];     // fp16 W1 fragment images
__device__ __align__(16) uint32_t g_b2h[NBIAS];    // permuted fc_b2, half2 pairs, [c][q][g8]
__device__ float g_accum[NNODES * 96];
__device__ float g_ps1[NSC];                       // partial sums (scalar channels)
__device__ float g_ps2[NSC + NVC];                 // partial sumsq (48 scalar + 16 vector bins)
__device__ int g_src[NEDGES];
__device__ int g_dst[NEDGES];

// ================= helpers =================
__device__ __forceinline__ uint32_t smem_u32(const void* p) {
    uint32_t a;
    asm("{ .reg .u64 t; cvta.to.shared.u64 t, %1; cvt.u32.u64 %0, t; }" : "=r"(a) : "l"(p));
    return a;
}
__device__ __forceinline__ void mma16(float* d, const uint32_t* a, uint32_t b0, uint32_t b1) {
    asm volatile(
        "mma.sync.aligned.m16n8k16.row.col.f32.f16.f16.f32 "
        "{%0,%1,%2,%3}, {%4,%5,%6,%7}, {%8,%9}, {%0,%1,%2,%3};\n"
        : "+f"(d[0]), "+f"(d[1]), "+f"(d[2]), "+f"(d[3])
        : "r"(a[0]), "r"(a[1]), "r"(a[2]), "r"(a[3]), "r"(b0), "r"(b1));
}
__device__ __forceinline__ void cpa16(uint32_t s, const void* g) {
    asm volatile("cp.async.ca.shared.global [%0], [%1], 16;" :: "r"(s), "l"(g));
}
#define CP_COMMIT() asm volatile("cp.async.commit_group;" ::: "memory")
#define CP_WAIT0()  asm volatile("cp.async.wait_group 0;" ::: "memory")

__device__ __forceinline__ float dlrelu(float x) { return (fabsf(x) <= 10.f) ? x : 0.01f * x; }
__device__ __forceinline__ uint32_t pack_relu(float a, float b) {
    __half2 h = __floats2half2_rn(fmaxf(a, 0.f), fmaxf(b, 0.f));
    return *reinterpret_cast<uint32_t*>(&h);
}

// 4-lane reduce-scatter over quad (lanes differ in bits 0..1 = q).
__device__ __forceinline__ float rs4(float v00, float v01, float v10, float v11, int q) {
    float k0 = (q & 1) ? v01 : v00;
    float s0 = (q & 1) ? v00 : v01;
    float k1 = (q & 1) ? v11 : v10;
    float s1 = (q & 1) ? v10 : v11;
    k0 += __shfl_xor_sync(0xffffffffu, s0, 1);
    k1 += __shfl_xor_sync(0xffffffffu, s1, 1);
    float k = (q >> 1) ? k1 : k0;
    float s = (q >> 1) ? k0 : k1;
    return k + __shfl_xor_sync(0xffffffffu, s, 2);
}

// column permutation: jp (permuted) -> original j of fc_w2
__device__ __forceinline__ int jorig_of(int jp) {
    int chunk = jp >> 6, q = jp & 63;
    if (chunk < 48) {
        return (q < 48) ? q * 48 + chunk : 2304 + (q - 48) * 48 + chunk;
    }
    int k = chunk - 48;
    return (q < 48) ? 3072 + q * 16 + k : 3840 + (q - 48) * 16 + k;
}

// ================= merged prep kernel =================
// dtype detect + idx convert + accum init + stats-bin zero + all fragment images
__global__ void k_prep(const int* __restrict__ raw, const float* __restrict__ na,
                       const float* __restrict__ w2, const float* __restrict__ b2,
                       const float* __restrict__ w1) {
    int idx = blockIdx.x * 256 + threadIdx.x;
    int local = (idx < NEDGES && raw[2 * idx + 1] != 0) ? 1 : 0;
    int is32 = __syncthreads_or(local);
    if (idx < NEDGES) {
        if (is32) { g_src[idx] = raw[idx]; g_dst[idx] = raw[NEDGES + idx]; }
        else      { g_src[idx] = raw[2 * idx]; g_dst[idx] = raw[2 * (NEDGES + idx)]; }
    }
    if (idx < NNODES * 96) g_accum[idx] = na[idx];
    if (idx < NSC) g_ps1[idx] = 0.f;
    if (idx < NSC + NVC) g_ps2[idx] = 0.f;

    if (idx < NBF_TOTAL) {
        int lane = idx & 31;
        int g8 = (idx >> 5) & 7;
        int rest = idx >> 8;        // chunk*8 + s
        int s = rest & 7, chunk = rest >> 3;
        int q = g8 * 8 + (lane >> 2);
        int jo = jorig_of(chunk * 64 + q);
        int k0 = s * 16 + (lane & 3) * 2;
        float f[4];
#pragma unroll
        for (int r = 0; r < 4; ++r) {
            int k = k0 + (r >> 1) * 8 + (r & 1);
            f[r] = w2[(size_t)k * WNUM + jo];
        }
        uint2 out;
        __half2 h0 = __floats2half2_rn(f[0], f[1]);
        __half2 h1 = __floats2half2_rn(f[2], f[3]);
        out.x = *reinterpret_cast<uint32_t*>(&h0);
        out.y = *reinterpret_cast<uint32_t*>(&h1);
        int pos = chunk * BFRAG_PER_CHUNK + (s * 4 + (g8 >> 1)) * 64 + lane * 2 + (g8 & 1);
        g_Bfrag[pos] = out;
    } else if (idx < NBF_TOTAL + NW1F) {
        int v = idx - NBF_TOTAL;
        int lane = v & 31;
        int g = (v >> 5) & 15;
        int s = v >> 9;             // 0..7
        int col = g * 8 + (lane >> 2);
        int k0 = s * 16 + (lane & 3) * 2;
        float f[4];
#pragma unroll
        for (int r = 0; r < 4; ++r) {
            int k = k0 + (r >> 1) * 8 + (r & 1);
            f[r] = w1[k * 128 + col];
        }
        uint2 out;
        __half2 h0 = __floats2half2_rn(f[0], f[1]);
        __half2 h1 = __floats2half2_rn(f[2], f[3]);
        out.x = *reinterpret_cast<uint32_t*>(&h0);
        out.y = *reinterpret_cast<uint32_t*>(&h1);
        g_W1frag[v] = out;
    } else if (idx < NBF_TOTAL + NW1F + NBIAS) {
        int v = idx - NBF_TOTAL - NW1F;
        int c = v >> 5, i = v & 31;
        int q = i >> 3, g8 = i & 7;       // layout [c][q][g8]
        int q0 = g8 * 8 + q * 2;
        __half2 h = __floats2half2_rn(b2[jorig_of(c * 64 + q0)],
                                      b2[jorig_of(c * 64 + q0 + 1)]);
        g_b2h[v] = *reinterpret_cast<uint32_t*>(&h);
    }
}

// ================= fused stage-A + fp16 mma GEMM + tensor product + scatter =================
struct SmemT {
    uint2 B[2][BFRAG_PER_CHUNK];   // 32768 B — holds W1frag during prologue
    union {
        __half eah[EPT * 144];     // 36864 B (prologue ea image)
        struct {
            __half2 T1[EPT * 36];  // 18432: [el][q][g8] xs pairs (g8<6) / dot pairs (g8>=6)
            __half2 xvp[EPT][25];  // 12800
            uint32_t bias[NBIAS];  // 8192: [c][q][g8]
        } d;                       // 39424
    } u;
};   // total 72192 B -> 2 CTAs/SM (256 threads each)

extern __shared__ __align__(16) char smemraw[];

__global__ __launch_bounds__(256, 2) void k_tp(const float* __restrict__ na,
                                               const float* __restrict__ sh,
                                               const float* __restrict__ ea,
                                               const float* __restrict__ b1) {
    SmemT& sm = *reinterpret_cast<SmemT*>(smemraw);
    int t = threadIdx.x, lane = t & 31, w = t >> 5;
    int h = w & 1;                 // n-half
    int mb = (w >> 1) * 32;        // m-block base: 0,32,64,96
    int ebase = blockIdx.x * EPT;
    int r = lane >> 2, q = lane & 3;

    // per-thread fixed output edge (used only at the final atomics)
    int el_sel = mb + (q >> 1) * 16 + (q & 1) * 8 + r;
    float* arow;
    float sss_sel, sv_sel0, sv_sel1, sv_sel2;
    {
        int e = ebase + el_sel;
        arow = g_accum + (size_t)g_dst[e] * 96;
        float4 shv = __ldg(reinterpret_cast<const float4*>(sh) + e);
        sss_sel = shv.x; sv_sel0 = shv.y; sv_sel1 = shv.z; sv_sel2 = shv.w;
    }

    // ---- 1: stream W1 fragment images into the B double-buffer area (32 KB) ----
    {
        uint32_t sB = smem_u32(&sm.B[0][0]);
        const char* g = (const char*)g_W1frag;
#pragma unroll
        for (int i = 0; i < 8; ++i) cpa16(sB + (t + 256 * i) * 16, g + (t + 256 * i) * 16);
        CP_COMMIT();
    }
    // ---- 2: ea tile -> fp16 permuted smem image ----
    __half* eah = sm.u.eah;
    for (int i = t; i < EPT * 64; i += 256) {
        int e = i >> 6, c = (i & 63) * 2;
        float2 v = *reinterpret_cast<const float2*>(ea + (size_t)(ebase + e) * 128 + c);
        int s = c >> 4, ww = c & 15;
        int pos = ((ww & 7) >> 1) * 4 + ((ww >> 3) << 1);
        __half2 hp = __floats2half2_rn(v.x, v.y);
        *reinterpret_cast<__half2*>(eah + e * 144 + s * 16 + pos) = hp;
    }
    CP_WAIT0();
    __syncthreads();

    // ---- 3: prologue MMA — compute H fragments; b1 folded into acc init ----
    uint32_t afr[2][KS][4];
    const uint2* w1f = reinterpret_cast<const uint2*>(&sm.B[0][0]);
    const float2* b1f2 = reinterpret_cast<const float2*>(b1);
#pragma unroll
    for (int mt = 0; mt < 2; ++mt) {
        float accH[16][4];
#pragma unroll
        for (int g = 0; g < 16; ++g) {
            float2 bv = __ldg(&b1f2[g * 4 + q]);
            accH[g][0] = bv.x; accH[g][1] = bv.y;
            accH[g][2] = bv.x; accH[g][3] = bv.y;
        }
        const __half* row0 = eah + (mb + mt * 16 + r) * 144;
        const __half* row8 = row0 + 8 * 144;
#pragma unroll 1
        for (int s = 0; s < KS; ++s) {
            uint2 ae0 = *reinterpret_cast<const uint2*>(row0 + s * 16 + q * 4);
            uint2 ae1 = *reinterpret_cast<const uint2*>(row8 + s * 16 + q * 4);
            uint32_t af[4] = {ae0.x, ae1.x, ae0.y, ae1.y};
#pragma unroll
            for (int g = 0; g < 16; ++g) {
                uint2 bf = w1f[(s * 16 + g) * 32 + lane];
                mma16(accH[g], af, bf.x, bf.y);
            }
        }
#pragma unroll
        for (int sp = 0; sp < KS; ++sp) {
            afr[mt][sp][0] = pack_relu(accH[2 * sp][0], accH[2 * sp][1]);
            afr[mt][sp][1] = pack_relu(accH[2 * sp][2], accH[2 * sp][3]);
            afr[mt][sp][2] = pack_relu(accH[2 * sp + 1][0], accH[2 * sp + 1][1]);
            afr[mt][sp][3] = pack_relu(accH[2 * sp + 1][2], accH[2 * sp + 1][3]);
        }
    }
    __syncthreads();   // all warps done reading W1frag / ea_h

    // ---- 4: start B pipeline (chunk 0 -> buf 0) + bias table ----
    {
        uint32_t sB = smem_u32(&sm.B[0][0]);
        const char* g = (const char*)g_Bfrag;
#pragma unroll
        for (int i = 0; i < 4; ++i) cpa16(sB + (t + 256 * i) * 16, g + (t + 256 * i) * 16);
        uint32_t sBias = smem_u32(&sm.u.d.bias[0]);
        const char* gb = (const char*)g_b2h;
#pragma unroll
        for (int i = 0; i < 2; ++i) cpa16(sBias + (t + 256 * i) * 16, gb + (t + 256 * i) * 16);
        CP_COMMIT();
    }
    // ---- 5: per-edge node data -> packed tables (overwrites dead ea image) ----
    if (t < EPT) {
        int e = ebase + t;
        float4 shv = __ldg(reinterpret_cast<const float4*>(sh) + e);
        __half* t1h = reinterpret_cast<__half*>(&sm.u.d.T1[(size_t)t * 36]);
        __half* xvh = reinterpret_cast<__half*>(&sm.u.d.xvp[t][0]);
        const float4* nr = reinterpret_cast<const float4*>(na + (size_t)g_src[e] * 96);
        float dac[16];
#pragma unroll
        for (int i = 0; i < 16; ++i) dac[i] = 0.f;
        float svm[3] = {shv.y, shv.z, shv.w};
#pragma unroll
        for (int qq = 0; qq < 24; ++qq) {
            float4 v = __ldg(nr + qq);
            float vv[4] = {v.x, v.y, v.z, v.w};
#pragma unroll
            for (int jj = 0; jj < 4; ++jj) {
                int c = qq * 4 + jj;
                if (c < 48) {
                    int g8 = c >> 3, qi = (c >> 1) & 3, j = c & 1;
                    t1h[(qi * 8 + g8) * 2 + j] = __float2half(vv[jj]);
                } else {
                    int d = c - 48;
                    int i = d / 3, m = d % 3;
                    dac[i] += vv[jj] * svm[m];
                    xvh[((i >> 1) * 3 + m) * 2 + (i & 1)] = __float2half(vv[jj]);
                }
            }
        }
#pragma unroll
        for (int i = 0; i < 16; ++i) {
            int g8 = 6 + (i >> 3), qi = (i >> 1) & 3, j = i & 1;
            t1h[(qi * 8 + g8) * 2 + j] = __float2half(INV_SQRT3 * dac[i]);
        }
    }

    // ---- 6: main loop ----
#pragma unroll 1
    for (int c = 0; c < NCHUNKS; ++c) {
        int p = c & 1;
        CP_WAIT0();
        __syncthreads();
        if (c + 1 < NCHUNKS) {
            uint32_t sB = smem_u32(&sm.B[1 - p][0]);
            const char* g = (const char*)(g_Bfrag + (size_t)(c + 1) * BFRAG_PER_CHUNK);
#pragma unroll
            for (int i = 0; i < 4; ++i) cpa16(sB + (t + 256 * i) * 16, g + (t + 256 * i) * 16);
        }
        CP_COMMIT();
        // ---- MMA: m32 x n32 per warp, K=128, LDS.128 B loads ----
        float acc[2][4][4];
#pragma unroll
        for (int mt = 0; mt < 2; ++mt)
#pragma unroll
            for (int b = 0; b < 4; ++b)
#pragma unroll
                for (int rr = 0; rr < 4; ++rr) acc[mt][b][rr] = 0.f;
#pragma unroll
        for (int s = 0; s < KS; ++s) {
#pragma unroll
            for (int pp = 0; pp < 2; ++pp) {
                uint4 bf = *reinterpret_cast<const uint4*>(
                    &sm.B[p][(s * 4 + h * 2 + pp) * 64 + lane * 2]);
                mma16(acc[0][2 * pp],     afr[0][s], bf.x, bf.y);
                mma16(acc[1][2 * pp],     afr[1][s], bf.x, bf.y);
                mma16(acc[0][2 * pp + 1], afr[0][s], bf.z, bf.w);
                mma16(acc[1][2 * pp + 1], afr[1][s], bf.z, bf.w);
            }
        }
        // ---- epilogue ----
        uint4 bw = *reinterpret_cast<const uint4*>(&sm.u.d.bias[c * 32 + q * 8 + h * 4]);
        float2 bb[4];
        {
            const __half2* bh = reinterpret_cast<const __half2*>(&bw);
#pragma unroll
            for (int b = 0; b < 4; ++b) bb[b] = __half22float2(bh[b]);
        }
        if (c < 48) {
            float pxs[2][2] = {{0.f, 0.f}, {0.f, 0.f}};
            float pdot[2][2] = {{0.f, 0.f}, {0.f, 0.f}};
#pragma unroll
            for (int mt = 0; mt < 2; ++mt) {
#pragma unroll
                for (int rh = 0; rh < 2; ++rh) {
                    int el = mb + mt * 16 + rh * 8 + r;
                    uint4 cv = *reinterpret_cast<const uint4*>(
                        &sm.u.d.T1[el * 36 + q * 8 + h * 4]);
                    const __half2* ch = reinterpret_cast<const __half2*>(&cv);
#pragma unroll
                    for (int b = 0; b < 4; ++b) {
                        float2 cf = __half22float2(ch[b]);
                        float w0 = dlrelu(acc[mt][b][rh * 2 + 0] + bb[b].x);
                        float w1 = dlrelu(acc[mt][b][rh * 2 + 1] + bb[b].y);
                        if (h * 4 + b < 6) pxs[mt][rh] += cf.x * w0 + cf.y * w1;
                        else               pdot[mt][rh] += cf.x * w0 + cf.y * w1;
                    }
                }
            }
            float xsj = rs4(pxs[0][0], pxs[0][1], pxs[1][0], pxs[1][1], q);
            float dtj = rs4(pdot[0][0], pdot[0][1], pdot[1][0], pdot[1][1], q);
            atomicAdd(arow + c, ALPHA * fmaf(sss_sel, xsj, dtj));
        } else {
            int kk = c - 48;
            float t1[2][2] = {{0.f, 0.f}, {0.f, 0.f}};
            float tv[2][2][3];
#pragma unroll
            for (int mt = 0; mt < 2; ++mt)
#pragma unroll
                for (int rh = 0; rh < 2; ++rh)
#pragma unroll
                    for (int m = 0; m < 3; ++m) tv[mt][rh][m] = 0.f;
#pragma unroll
            for (int mt = 0; mt < 2; ++mt) {
#pragma unroll
                for (int rh = 0; rh < 2; ++rh) {
                    int el = mb + mt * 16 + rh * 8 + r;
                    uint4 cv = *reinterpret_cast<const uint4*>(
                        &sm.u.d.T1[el * 36 + q * 8 + h * 4]);
                    const __half2* ch = reinterpret_cast<const __half2*>(&cv);
#pragma unroll
                    for (int b = 0; b < 4; ++b) {
                        int g8 = h * 4 + b;
                        float w0 = dlrelu(acc[mt][b][rh * 2 + 0] + bb[b].x);
                        float w1 = dlrelu(acc[mt][b][rh * 2 + 1] + bb[b].y);
                        if (g8 < 6) {
                            float2 cf = __half22float2(ch[b]);
                            t1[mt][rh] += cf.x * w0 + cf.y * w1;
                        } else {
                            int ip = (g8 - 6) * 4 + q;
#pragma unroll
                            for (int m = 0; m < 3; ++m) {
                                float2 v0 = __half22float2(sm.u.d.xvp[el][ip * 3 + m]);
                                tv[mt][rh][m] += v0.x * w0 + v0.y * w1;
                            }
                        }
                    }
                }
            }
            float t1j = rs4(t1[0][0], t1[0][1], t1[1][0], t1[1][1], q);
            float tvj[3];
#pragma unroll
            for (int m = 0; m < 3; ++m)
                tvj[m] = rs4(tv[0][0][m], tv[0][1][m], tv[1][0][m], tv[1][1][m], q);
            float* base = arow + 48 + 3 * kk;
            atomicAdd(base + 0, ALPHA * fmaf(t1j, sv_sel0, sss_sel * tvj[0]));
            atomicAdd(base + 1, ALPHA * fmaf(t1j, sv_sel1, sss_sel * tvj[1]));
            atomicAdd(base + 2, ALPHA * fmaf(t1j, sv_sel2, sss_sel * tvj[2]));
        }
    }
}

// ---------------- batchnorm statistics: coalesced partial reduction ----------------
__global__ __launch_bounds__(192) void k_stats_part() {
    __shared__ float sh1[96], sh2[96];
    int t = threadIdx.x;
    int col = t % 96, ro = t / 96;      // ro in {0,1}
    float s1 = 0.f, s2 = 0.f;
    const float* p = g_accum + (size_t)(blockIdx.x * 32 + ro) * 96 + col;
#pragma unroll 4
    for (int i = 0; i < 16; ++i) {
        float x = p[(size_t)i * 192];   // advance 2 node-rows
        s1 += x;
        s2 += x * x;
    }
    if (ro == 1) { sh1[col] = s1; sh2[col] = s2; }
    __syncthreads();
    if (ro == 0) {
        s1 += sh1[col];
        s2 += sh2[col];
        if (col < NSC) {
            atomicAdd(&g_ps1[col], s1);
            atomicAdd(&g_ps2[col], s2);
        } else {
            int k = (col - NSC) / 3;
            atomicAdd(&g_ps2[NSC + k], s2);
        }
    }
}

// finalize + normalize in one kernel (per-thread finalization from partial bins)
__global__ void k_final(const float* __restrict__ bnw, const float* __restrict__ bnb,
                        float* __restrict__ out) {
    int idx = blockIdx.x * 256 + threadIdx.x;
    if (idx >= NNODES * 96) return;
    int c = idx % 96;
    float x = g_accum[idx];
    float o;
    if (c < NSC) {
        float mean = g_ps1[c] * (1.0f / NNODES);
        float var = g_ps2[c] * (1.0f / NNODES) - mean * mean;
        float rs = rsqrtf(var + BN_EPS) * bnw[c];
        o = (x - mean) * rs + bnb[c];
    } else {
        int k = (c - 48) / 3;
        float vn = g_ps2[NSC + k] * (1.0f / (3.0f * NNODES));
        o = x * rsqrtf(vn + BN_EPS) * bnw[NSC + k];
    }
    out[idx] = o;
}

// ---------------- launch ----------------
extern "C" void kernel_launch(void* const* d_in, const int* in_sizes, int n_in,
                              void* d_out, int out_size) {
    const float* node_attr = (const float*)d_in[0];
    const int* eidx_raw    = (const int*)d_in[1];
    const float* edge_attr = (const float*)d_in[2];
    const float* edge_sh   = (const float*)d_in[3];
    const float* fc_w1     = (const float*)d_in[4];
    const float* fc_b1     = (const float*)d_in[5];
    const float* fc_w2     = (const float*)d_in[6];
    const float* fc_b2     = (const float*)d_in[7];
    const float* bn_weight = (const float*)d_in[8];
    const float* bn_bias   = (const float*)d_in[9];
    float* out = (float*)d_out;

    cudaFuncSetAttribute(k_tp, cudaFuncAttributeMaxDynamicSharedMemorySize,
                         (int)sizeof(SmemT));

    k_prep<<<(NNODES * 96 + 255) / 256, 256>>>(eidx_raw, node_attr, fc_w2, fc_b2, fc_w1);
    k_tp<<<NEDGES / EPT, 256, sizeof(SmemT)>>>(node_attr, edge_sh, edge_attr, fc_b1);
    k_stats_part<<<NNODES / 32, 192>>>();
    k_final<<<(NNODES * 96 + 255) / 256, 256>>>(bn_weight, bn_bias, out);
}